// round 14
// baseline (speedup 1.0000x reference)
#include <cuda_runtime.h>
#include <cuda_fp16.h>
#include <math.h>
#include <stdint.h>

#define BATCH   2
#define LSEQ    2048
#define MTOK    (BATCH*LSEQ)          // 4096
#define DMODEL  2048
#define DINNER  2048
#define NH      32
#define DSTATE  64
#define HD      64
#define CHUNK   128
#define NCHUNK  (LSEQ/CHUNK)          // 16
#define DFF     8192
#define CONVD   (DINNER + 2*NH*DSTATE)          // 6144
#define DINPROJ (2*DINNER + 2*NH*DSTATE + NH)   // 8224
#define DTOFF   (DINNER + CONVD)                // 8192

// ------------------------- scratch (device globals, no allocs) -------------
__device__ float g_zx  [(size_t)MTOK*DINPROJ];
__device__ float g_xBC [(size_t)MTOK*CONVD];
__device__ float g_y   [(size_t)MTOK*DINNER];
__device__ float g_S   [(size_t)BATCH*NCHUNK*NH*DSTATE*HD];
__device__ float g_Ac  [(size_t)BATCH*NCHUNK*NH];
__device__ float g_cum [(size_t)BATCH*NCHUNK*NH*CHUNK];
__device__ float g_Hp  [(size_t)BATCH*NCHUNK*NH*DSTATE*HD];
__device__ float g_h2  [(size_t)MTOK*DMODEL];
__device__ float g_gate[(size_t)MTOK*DFF];
__device__ float g_up  [(size_t)MTOK*DFF];
// fp16 GEMM activation inputs
__device__ __half g_h1h [(size_t)MTOK*DMODEL];
__device__ __half g_yh  [(size_t)MTOK*DINNER];
__device__ __half g_h3h [(size_t)MTOK*DMODEL];
__device__ __half g_acth[(size_t)MTOK*DFF];
// fp16 weight copies
__device__ __half g_wip [(size_t)DINPROJ*DMODEL];
__device__ __half g_wop [(size_t)DMODEL*DINNER];
__device__ __half g_wg  [(size_t)DFF*DMODEL];
__device__ __half g_wu  [(size_t)DFF*DMODEL];
__device__ __half g_wd  [(size_t)DMODEL*DFF];

// ------------------------------ helpers ------------------------------------
__device__ __forceinline__ uint32_t smem_u32(const void* p) {
    uint32_t r;
    asm("{ .reg .u64 t; cvta.to.shared.u64 t, %1; cvt.u32.u64 %0, t; }" : "=r"(r) : "l"(p));
    return r;
}
__device__ __forceinline__ void cpa16(uint32_t dst, const void* src, int bytes) {
    asm volatile("cp.async.cg.shared.global [%0], [%1], 16, %2;\n"
                 :: "r"(dst), "l"(src), "r"(bytes));
}
__device__ __forceinline__ void cpa_commit() { asm volatile("cp.async.commit_group;\n"); }
__device__ __forceinline__ void cpa_wait0()  { asm volatile("cp.async.wait_group 0;\n"); }
__device__ __forceinline__ void cpa_wait1()  { asm volatile("cp.async.wait_group 1;\n"); }
__device__ __forceinline__ void cpa_wait2()  { asm volatile("cp.async.wait_group 2;\n"); }

#define LDSM4(r0, r1, r2, r3, addr) \
    asm volatile("ldmatrix.sync.aligned.m8n8.x4.shared.b16 {%0,%1,%2,%3}, [%4];" \
        : "=r"(r0), "=r"(r1), "=r"(r2), "=r"(r3) : "r"(addr))

// fp32 -> fp16 weight conversion (float4 -> 4 halves)
__global__ void w2h_kernel(const float* __restrict__ in, __half* __restrict__ out, int n4) {
    int i = blockIdx.x * blockDim.x + threadIdx.x;
    if (i < n4) {
        float4 v = ((const float4*)in)[i];
        __half2 h0 = __floats2half2_rn(v.x, v.y);
        __half2 h1 = __floats2half2_rn(v.z, v.w);
        uint2 st;
        st.x = *(uint32_t*)&h0;
        st.y = *(uint32_t*)&h1;
        ((uint2*)out)[i] = st;
    }
}

// ------------------------------ rmsnorm (fp16 output) -----------------------
__global__ void rmsnorm_kernel(const float* __restrict__ x, const float* __restrict__ w,
                               __half* __restrict__ y) {
    int row = blockIdx.x;
    const float* xr = x + (size_t)row * DMODEL;
    float ss = 0.f;
    for (int c = threadIdx.x; c < DMODEL; c += 256) { float v = xr[c]; ss += v * v; }
    #pragma unroll
    for (int off = 16; off; off >>= 1) ss += __shfl_xor_sync(0xffffffffu, ss, off);
    __shared__ float red[8];
    if ((threadIdx.x & 31) == 0) red[threadIdx.x >> 5] = ss;
    __syncthreads();
    if (threadIdx.x < 8) {
        float v = red[threadIdx.x];
        #pragma unroll
        for (int off = 4; off; off >>= 1) v += __shfl_xor_sync(0xffu, v, off);
        if (threadIdx.x == 0) red[0] = v;
    }
    __syncthreads();
    float inv = rsqrtf(red[0] / (float)DMODEL + 1e-5f);
    __half* yr = y + (size_t)row * DMODEL;
    for (int c = threadIdx.x; c < DMODEL; c += 256)
        yr[c] = __float2half_rn(w[c] * xr[c] * inv);
}

// ------------------------------ FP16 tensor-core GEMM -----------------------
// C(fp32) = A(fp16) * W(fp16)^T (+ res fp32). A:[M,K], W:[N,K] row-major.
// CTA tile 128x256, BK=64, 8 warps of 64x64, mma.sync.m16n8k16.f16 (fp32 acc),
// ldmatrix fragment loads, 4-stage cp.async pipeline, 1 sync/iter.
#define HROW 144                 // bytes per smem row (64 halves + 8 pad)
#define ASTGB (128 * HROW)       // A stage bytes  (18432)
#define BSTGB (256 * HROW)       // B stage bytes  (36864)
#define STGB  (ASTGB + BSTGB)    // 55296
#define SMEM_HGEMM (4 * STGB)    // 221184

__global__ __launch_bounds__(256, 1) void hgemm_kernel(
        const __half* __restrict__ A, const __half* __restrict__ W,
        const float* __restrict__ res, float* __restrict__ C,
        int M, int N, int K) {
    extern __shared__ char smraw[];
    const uint32_t sb = smem_u32(smraw);

    int tid = threadIdx.x;
    int bm = blockIdx.y * 128, bn = blockIdx.x * 256;
    int lane = tid & 31, warp = tid >> 5;
    int wm = (warp >> 2) * 64;       // 0 or 64
    int wn = (warp & 3) * 64;        // 0..192
    int grp = lane >> 2, tig = lane & 3;

    // ldmatrix per-lane address components (mat = lane>>3, r = lane&7)
    int mat = lane >> 3, r = lane & 7;
    uint32_t a_off = (uint32_t)(((mat & 1) * 8 + r) * HROW + (mat >> 1) * 16);
    uint32_t b_off = (uint32_t)(((mat >> 1) * 8 + r) * HROW + (mat & 1) * 16);

    float c[4][8][4];
    #pragma unroll
    for (int mt = 0; mt < 4; mt++)
        #pragma unroll
        for (int nt = 0; nt < 8; nt++)
            #pragma unroll
            for (int e = 0; e < 4; e++) c[mt][nt][e] = 0.f;

    const int ldrow = tid >> 3;        // 0..31
    const int c16   = tid & 7;         // 16B chunk (8 halves)

    auto load_tile = [&](int t, int which) {
        int kb = t * 64;
        uint32_t ab = sb + (uint32_t)which * STGB;
        uint32_t wb = ab + ASTGB;
        #pragma unroll
        for (int i = 0; i < 4; i++) {          // A: 128 rows
            int row = ldrow + i * 32;
            cpa16(ab + row * HROW + c16 * 16,
                  A + (size_t)(bm + row) * K + kb + c16 * 8, 16);
        }
        #pragma unroll
        for (int i = 0; i < 8; i++) {          // B: 256 rows
            int row = ldrow + i * 32;
            int n = bn + row;
            int nn = n < N ? n : (N - 1);
            cpa16(wb + row * HROW + c16 * 16,
                  W + (size_t)nn * K + kb + c16 * 8, n < N ? 16 : 0);
        }
    };

    int ntiles = K / 64;              // >= 32 for all our shapes
    load_tile(0, 0); cpa_commit();
    load_tile(1, 1); cpa_commit();
    load_tile(2, 2); cpa_commit();

    for (int t = 0; t < ntiles; t++) {
        int rem = ntiles - t - 1;
        if (rem >= 2) cpa_wait2();
        else if (rem == 1) cpa_wait1();
        else cpa_wait0();
        __syncthreads();
        if (t + 3 < ntiles) { load_tile(t + 3, (t + 3) & 3); cpa_commit(); }

        int buf = t & 3;
        uint32_t ab = sb + (uint32_t)buf * STGB;
        uint32_t wb = ab + ASTGB;
        uint32_t abase = ab + (uint32_t)wm * HROW + a_off;
        uint32_t bbase = wb + (uint32_t)wn * HROW + b_off;
        #pragma unroll
        for (int ks = 0; ks < 4; ks++) {
            uint32_t kbyte = (uint32_t)ks * 32;   // 16 halves
            uint32_t af[4][4], bf[8][2];
            #pragma unroll
            for (int mt = 0; mt < 4; mt++)
                LDSM4(af[mt][0], af[mt][1], af[mt][2], af[mt][3],
                      abase + (uint32_t)mt * 16 * HROW + kbyte);
            #pragma unroll
            for (int ntp = 0; ntp < 4; ntp++)
                LDSM4(bf[2*ntp][0], bf[2*ntp][1], bf[2*ntp+1][0], bf[2*ntp+1][1],
                      bbase + (uint32_t)ntp * 16 * HROW + kbyte);
            #pragma unroll
            for (int mt = 0; mt < 4; mt++)
                #pragma unroll
                for (int nt = 0; nt < 8; nt++) {
                    asm volatile(
                        "mma.sync.aligned.m16n8k16.row.col.f32.f16.f16.f32 "
                        "{%0,%1,%2,%3}, {%4,%5,%6,%7}, {%8,%9}, {%0,%1,%2,%3};\n"
                        : "+f"(c[mt][nt][0]), "+f"(c[mt][nt][1]),
                          "+f"(c[mt][nt][2]), "+f"(c[mt][nt][3])
                        : "r"(af[mt][0]), "r"(af[mt][1]), "r"(af[mt][2]), "r"(af[mt][3]),
                          "r"(bf[nt][0]), "r"(bf[nt][1]));
                }
        }
    }

    // epilogue
    #pragma unroll
    for (int mt = 0; mt < 4; mt++) {
        int r0 = bm + wm + mt * 16 + grp;
        #pragma unroll
        for (int nt = 0; nt < 8; nt++) {
            int col = bn + wn + nt * 8 + 2 * tig;
            if (col < N) {
                float v0 = c[mt][nt][0], v1 = c[mt][nt][1];
                float v2 = c[mt][nt][2], v3 = c[mt][nt][3];
                size_t o0 = (size_t)r0 * N + col;
                size_t o1 = (size_t)(r0 + 8) * N + col;
                if (res) {
                    v0 += res[o0]; v1 += res[o0 + 1];
                    v2 += res[o1]; v3 += res[o1 + 1];
                }
                *(float2*)(C + o0) = make_float2(v0, v1);
                *(float2*)(C + o1) = make_float2(v2, v3);
            }
        }
    }
}

// ------------------------------ causal depthwise conv ----------------------
__global__ void conv1d_kernel(const float* __restrict__ zx, const float* __restrict__ cw,
                              const float* __restrict__ cb, float* __restrict__ xBC) {
    size_t idx = (size_t)blockIdx.x * blockDim.x + threadIdx.x;
    if (idx >= (size_t)MTOK * CONVD) return;
    int c = (int)(idx % CONVD);
    int m = (int)(idx / CONVD);
    int t = m & (LSEQ - 1);
    float acc = cb[c];
    #pragma unroll
    for (int j = 0; j < 4; j++) {
        int tt = t - 3 + j;
        if (tt >= 0)
            acc += cw[c * 4 + j] * zx[(size_t)(m - 3 + j) * DINPROJ + DINNER + c];
    }
    xBC[idx] = acc;
}

// ------------------------------ SSD intra-chunk (512 threads) ---------------
__global__ void ssd_intra_kernel(const float* __restrict__ zx, const float* __restrict__ xBC,
                                 float* __restrict__ y, float* __restrict__ Sg,
                                 float* __restrict__ Ag, float* __restrict__ cumg) {
    extern __shared__ float sm[];
    float* xs   = sm;                       // 128*65
    float* Bs   = xs + CHUNK * 65;          // 128*65
    float* Cs   = Bs + CHUNK * 65;          // 128*65
    float* sc   = Cs + CHUNK * 65;          // 128*129
    float* cum  = sc + CHUNK * 129;         // 128
    float* dend = cum + CHUNK;              // 128

    int h = blockIdx.x % NH;
    int c = (blockIdx.x / NH) % NCHUNK;
    int b = blockIdx.x / (NH * NCHUNK);
    int tid = threadIdx.x;
    int m0 = b * LSEQ + c * CHUNK;

    for (int idx = tid; idx < CHUNK * HD; idx += 512) {
        int i = idx >> 6, p = idx & 63;
        size_t rowb = (size_t)(m0 + i) * CONVD;
        xs[i * 65 + p] = xBC[rowb + h * HD + p];
        Bs[i * 65 + p] = xBC[rowb + DINNER + h * DSTATE + p];
        Cs[i * 65 + p] = xBC[rowb + DINNER + NH * DSTATE + h * DSTATE + p];
    }
    if (tid < CHUNK) {
        float d = zx[(size_t)(m0 + tid) * DINPROJ + DTOFF + h];
        float sp = (d > 20.f) ? d : log1pf(expf(d));
        cum[tid] = -sp;
    }
    __syncthreads();
    for (int off = 1; off < CHUNK; off <<= 1) {
        float v = 0.f;
        if (tid < CHUNK && tid >= off) v = cum[tid - off];
        __syncthreads();
        if (tid < CHUNK && tid >= off) cum[tid] += v;
        __syncthreads();
    }
    if (tid < CHUNK) dend[tid] = expf(cum[CHUNK - 1] - cum[tid]);
    __syncthreads();

    // Phase A: sc[i][j] = exp(cum_i - cum_j) * dot(C_i, B_j), i in 4-row strip
    {
        int ty = tid >> 4;          // 0..31
        int tx = tid & 15;
        int i0 = ty * 4;
        float acc[4][8];
        #pragma unroll
        for (int rr = 0; rr < 4; rr++)
            #pragma unroll
            for (int s = 0; s < 8; s++) acc[rr][s] = 0.f;
        for (int n = 0; n < DSTATE; n++) {
            float cf[4], bf[8];
            #pragma unroll
            for (int rr = 0; rr < 4; rr++) cf[rr] = Cs[(i0 + rr) * 65 + n];
            #pragma unroll
            for (int s = 0; s < 8; s++) bf[s] = Bs[(tx + 16 * s) * 65 + n];
            #pragma unroll
            for (int rr = 0; rr < 4; rr++)
                #pragma unroll
                for (int s = 0; s < 8; s++) acc[rr][s] += cf[rr] * bf[s];
        }
        #pragma unroll
        for (int rr = 0; rr < 4; rr++) {
            int i = i0 + rr;
            float ci = cum[i];
            #pragma unroll
            for (int s = 0; s < 8; s++) {
                int j = tx + 16 * s;
                sc[i * 129 + j] = (j <= i) ? expf(ci - cum[j]) * acc[rr][s] : 0.f;
            }
        }
    }
    __syncthreads();
    // Phase B: y_intra = sc @ x   (4 rows x 4 cols per thread)
    {
        int i0 = (tid >> 4) * 4;
        int p0 = (tid & 15) * 4;
        float acc[4][4];
        #pragma unroll
        for (int rr = 0; rr < 4; rr++)
            #pragma unroll
            for (int cc = 0; cc < 4; cc++) acc[rr][cc] = 0.f;
        for (int j = 0; j < CHUNK; j++) {
            float xv[4];
            #pragma unroll
            for (int cc = 0; cc < 4; cc++) xv[cc] = xs[j * 65 + p0 + cc];
            #pragma unroll
            for (int rr = 0; rr < 4; rr++) {
                float sf = sc[(i0 + rr) * 129 + j];
                #pragma unroll
                for (int cc = 0; cc < 4; cc++) acc[rr][cc] += sf * xv[cc];
            }
        }
        #pragma unroll
        for (int rr = 0; rr < 4; rr++) {
            size_t ybase = (size_t)(m0 + i0 + rr) * DINNER + h * HD + p0;
            #pragma unroll
            for (int cc = 0; cc < 4; cc++) y[ybase + cc] = acc[rr][cc];
        }
    }
    // Phase C: chunk state S[n][p] = sum_j dend[j]*B[j,n]*x[j,p] (8 cols/thread)
    {
        int n = tid >> 3;            // 0..63
        int p0 = (tid & 7) * 8;
        float acc[8];
        #pragma unroll
        for (int cc = 0; cc < 8; cc++) acc[cc] = 0.f;
        for (int j = 0; j < CHUNK; j++) {
            float w = dend[j] * Bs[j * 65 + n];
            #pragma unroll
            for (int cc = 0; cc < 8; cc++) acc[cc] += w * xs[j * 65 + p0 + cc];
        }
        size_t off = ((size_t)((b * NCHUNK + c) * NH + h)) * (DSTATE * HD) + n * HD + p0;
        #pragma unroll
        for (int cc = 0; cc < 8; cc++) Sg[off + cc] = acc[cc];
        if (tid == 0) Ag[(b * NCHUNK + c) * NH + h] = expf(cum[CHUNK - 1]);
    }
    if (tid < CHUNK)
        cumg[((size_t)((b * NCHUNK + c) * NH + h)) * CHUNK + tid] = cum[tid];
}

// ------------------------------ inter-chunk state recurrence ----------------
__global__ void state_scan_kernel(const float* __restrict__ Sg, const float* __restrict__ Ag,
                                  float* __restrict__ Hp) {
    int b = blockIdx.x / NH, h = blockIdx.x % NH;
    int tid = threadIdx.x;
    float H[16];
    #pragma unroll
    for (int k = 0; k < 16; k++) H[k] = 0.f;
    for (int c = 0; c < NCHUNK; c++) {
        size_t off = ((size_t)((b * NCHUNK + c) * NH + h)) * (DSTATE * HD);
        float Ac = Ag[(b * NCHUNK + c) * NH + h];
        #pragma unroll
        for (int k = 0; k < 16; k++) {
            int e = tid + k * 256;
            Hp[off + e] = H[k];
            H[k] = Ac * H[k] + Sg[off + e];
        }
    }
}

// ------------------------------ y_inter + D*x + gating (512 thr, fp16 out) --
__global__ void y_inter_kernel(const float* __restrict__ zx, const float* __restrict__ xBC,
                               const float* __restrict__ Hp, const float* __restrict__ cumg,
                               const float* __restrict__ Dvec, const float* __restrict__ zb,
                               const float* __restrict__ y, __half* __restrict__ yh) {
    extern __shared__ float sm[];
    float* Cs  = sm;                  // 128*65
    float* xs  = Cs + CHUNK * 65;     // 128*65
    float* Hs  = xs + CHUNK * 65;     // 64*65
    float* cum = Hs + DSTATE * 65;    // 128

    int h = blockIdx.x % NH;
    int c = (blockIdx.x / NH) % NCHUNK;
    int b = blockIdx.x / (NH * NCHUNK);
    int tid = threadIdx.x;
    int m0 = b * LSEQ + c * CHUNK;
    size_t hoff = (size_t)((b * NCHUNK + c) * NH + h);

    for (int idx = tid; idx < CHUNK * HD; idx += 512) {
        int i = idx >> 6, p = idx & 63;
        size_t rowb = (size_t)(m0 + i) * CONVD;
        xs[i * 65 + p] = xBC[rowb + h * HD + p];
        Cs[i * 65 + p] = xBC[rowb + DINNER + NH * DSTATE + h * DSTATE + p];
    }
    for (int idx = tid; idx < DSTATE * HD; idx += 512)
        Hs[(idx >> 6) * 65 + (idx & 63)] = Hp[hoff * (DSTATE * HD) + idx];
    if (tid < CHUNK) cum[tid] = cumg[hoff * CHUNK + tid];
    __syncthreads();

    int i = tid >> 2;                 // 0..127
    int p0 = (tid & 3) * 16;
    float acc[16];
    #pragma unroll
    for (int cc = 0; cc < 16; cc++) acc[cc] = 0.f;
    for (int n = 0; n < DSTATE; n++) {
        float cv = Cs[i * 65 + n];
        #pragma unroll
        for (int cc = 0; cc < 16; cc++) acc[cc] += cv * Hs[n * 65 + p0 + cc];
    }
    float e = expf(cum[i]);
    float Dh = Dvec[h];
    int m = m0 + i;
    size_t ybase = (size_t)m * DINNER + h * HD;
    size_t zbase = (size_t)m * DINPROJ + h * HD;
    #pragma unroll
    for (int cc = 0; cc < 16; cc++) {
        int p = p0 + cc;
        float yt = y[ybase + p] + e * acc[cc] + Dh * xs[i * 65 + p];
        float g = zx[zbase + p] + zb[h * HD + p];
        float sg = g / (1.f + expf(-g));
        yh[ybase + p] = __float2half_rn(yt * sg);
    }
}

// ------------------------------ MLP elementwise (fp16 out) ------------------
__global__ void silu_mul_kernel(const float* __restrict__ gate, const float* __restrict__ up,
                                __half* __restrict__ act, size_t n) {
    size_t i = (size_t)blockIdx.x * blockDim.x + threadIdx.x;
    if (i < n) {
        float g = gate[i];
        act[i] = __float2half_rn((g / (1.f + expf(-g))) * up[i]);
    }
}

// ------------------------------ launch --------------------------------------
extern "C" void kernel_launch(void* const* d_in, const int* in_sizes, int n_in,
                              void* d_out, int out_size) {
    const float* hidden     = (const float*)d_in[0];
    const float* in_proj_w  = (const float*)d_in[1];
    const float* z_bias     = (const float*)d_in[2];
    const float* conv_w     = (const float*)d_in[3];
    const float* conv_b     = (const float*)d_in[4];
    const float* Dvec       = (const float*)d_in[5];
    const float* out_proj_w = (const float*)d_in[6];
    const float* norm1_w    = (const float*)d_in[7];
    const float* norm2_w    = (const float*)d_in[8];
    const float* gate_w     = (const float*)d_in[9];
    const float* up_w       = (const float*)d_in[10];
    const float* down_w     = (const float*)d_in[11];
    float* out = (float*)d_out;

    float *zx, *xbc, *y, *S, *A, *cumg, *Hp, *h2, *gate, *up;
    __half *h1h, *yh, *h3h, *acth, *wip, *wop, *wg, *wu, *wd;
    cudaGetSymbolAddress((void**)&zx,   g_zx);
    cudaGetSymbolAddress((void**)&xbc,  g_xBC);
    cudaGetSymbolAddress((void**)&y,    g_y);
    cudaGetSymbolAddress((void**)&S,    g_S);
    cudaGetSymbolAddress((void**)&A,    g_Ac);
    cudaGetSymbolAddress((void**)&cumg, g_cum);
    cudaGetSymbolAddress((void**)&Hp,   g_Hp);
    cudaGetSymbolAddress((void**)&h2,   g_h2);
    cudaGetSymbolAddress((void**)&gate, g_gate);
    cudaGetSymbolAddress((void**)&up,   g_up);
    cudaGetSymbolAddress((void**)&h1h,  g_h1h);
    cudaGetSymbolAddress((void**)&yh,   g_yh);
    cudaGetSymbolAddress((void**)&h3h,  g_h3h);
    cudaGetSymbolAddress((void**)&acth, g_acth);
    cudaGetSymbolAddress((void**)&wip,  g_wip);
    cudaGetSymbolAddress((void**)&wop,  g_wop);
    cudaGetSymbolAddress((void**)&wg,   g_wg);
    cudaGetSymbolAddress((void**)&wu,   g_wu);
    cudaGetSymbolAddress((void**)&wd,   g_wd);

    const int SMEM_INTRA  = (3 * CHUNK * 65 + CHUNK * 129 + 2 * CHUNK) * sizeof(float);
    const int SMEM_YINTER = (2 * CHUNK * 65 + DSTATE * 65 + CHUNK) * sizeof(float);
    cudaFuncSetAttribute(ssd_intra_kernel, cudaFuncAttributeMaxDynamicSharedMemorySize, SMEM_INTRA);
    cudaFuncSetAttribute(y_inter_kernel,  cudaFuncAttributeMaxDynamicSharedMemorySize, SMEM_YINTER);
    cudaFuncSetAttribute(hgemm_kernel,    cudaFuncAttributeMaxDynamicSharedMemorySize, SMEM_HGEMM);

    // 0) convert weights fp32 -> fp16
    {
        auto cc = [&](const float* src, __half* dst, size_t n) {
            int n4 = (int)(n / 4);
            w2h_kernel<<<(n4 + 255) / 256, 256>>>(src, dst, n4);
        };
        cc(in_proj_w,  wip, (size_t)DINPROJ * DMODEL);
        cc(out_proj_w, wop, (size_t)DMODEL * DINNER);
        cc(gate_w,     wg,  (size_t)DFF * DMODEL);
        cc(up_w,       wu,  (size_t)DFF * DMODEL);
        cc(down_w,     wd,  (size_t)DMODEL * DFF);
    }

    // 1) rmsnorm 1 -> fp16
    rmsnorm_kernel<<<MTOK, 256>>>(hidden, norm1_w, h1h);
    // 2) in_proj: zx = h1 @ in_proj_w^T   [4096 x 8224]
    hgemm_kernel<<<dim3((DINPROJ + 255) / 256, MTOK / 128), 256, SMEM_HGEMM>>>(
        h1h, wip, nullptr, zx, MTOK, DINPROJ, DMODEL);
    // 3) causal depthwise conv
    conv1d_kernel<<<(int)(((size_t)MTOK * CONVD + 255) / 256), 256>>>(zx, conv_w, conv_b, xbc);
    // 4) SSD intra-chunk (512 threads)
    ssd_intra_kernel<<<BATCH * NCHUNK * NH, 512, SMEM_INTRA>>>(zx, xbc, y, S, A, cumg);
    // 5) inter-chunk state recurrence
    state_scan_kernel<<<BATCH * NH, 256>>>(S, A, Hp);
    // 6) y_inter + D*x + gating -> fp16 (512 threads)
    y_inter_kernel<<<BATCH * NCHUNK * NH, 512, SMEM_YINTER>>>(
        zx, xbc, Hp, cumg, Dvec, z_bias, y, yh);
    // 7) out_proj + residual: h2 = y @ out_proj_w^T + hidden
    hgemm_kernel<<<dim3(DMODEL / 256, MTOK / 128), 256, SMEM_HGEMM>>>(
        yh, wop, hidden, h2, MTOK, DMODEL, DINNER);
    // 8) rmsnorm 2 -> fp16
    rmsnorm_kernel<<<MTOK, 256>>>(h2, norm2_w, h3h);
    // 9) MLP gate / up
    hgemm_kernel<<<dim3(DFF / 256, MTOK / 128), 256, SMEM_HGEMM>>>(
        h3h, wg, nullptr, gate, MTOK, DFF, DMODEL);
    hgemm_kernel<<<dim3(DFF / 256, MTOK / 128), 256, SMEM_HGEMM>>>(
        h3h, wu, nullptr, up, MTOK, DFF, DMODEL);
    // 10) act = silu(gate) * up -> fp16
    silu_mul_kernel<<<(int)(((size_t)MTOK * DFF + 255) / 256), 256>>>(
        gate, up, acth, (size_t)MTOK * DFF);
    // 11) down + residual: out = act @ down_w^T + h2
    hgemm_kernel<<<dim3(DMODEL / 256, MTOK / 128), 256, SMEM_HGEMM>>>(
        acth, wd, h2, out, MTOK, DMODEL, DFF);
}

// round 15
// speedup vs baseline: 1.0537x; 1.0537x over previous
#include <cuda_runtime.h>
#include <cuda_fp16.h>
#include <math.h>
#include <stdint.h>

#define BATCH   2
#define LSEQ    2048
#define MTOK    (BATCH*LSEQ)          // 4096
#define DMODEL  2048
#define DINNER  2048
#define NH      32
#define DSTATE  64
#define HD      64
#define CHUNK   128
#define NCHUNK  (LSEQ/CHUNK)          // 16
#define DFF     8192
#define CONVD   (DINNER + 2*NH*DSTATE)          // 6144
#define DINPROJ (2*DINNER + 2*NH*DSTATE + NH)   // 8224
#define DTOFF   (DINNER + CONVD)                // 8192

// ------------------------- scratch (device globals, no allocs) -------------
__device__ float  g_zx  [(size_t)MTOK*DINPROJ];
__device__ __half g_xBC [(size_t)MTOK*CONVD];
__device__ float  g_y   [(size_t)MTOK*DINNER];
__device__ float  g_S   [(size_t)BATCH*NCHUNK*NH*DSTATE*HD];
__device__ float  g_Ac  [(size_t)BATCH*NCHUNK*NH];
__device__ float  g_cum [(size_t)BATCH*NCHUNK*NH*CHUNK];
__device__ float  g_Hp  [(size_t)BATCH*NCHUNK*NH*DSTATE*HD];
__device__ float  g_h2  [(size_t)MTOK*DMODEL];
// fp16 GEMM activation inputs / intermediates
__device__ __half g_h1h [(size_t)MTOK*DMODEL];
__device__ __half g_yh  [(size_t)MTOK*DINNER];
__device__ __half g_h3h [(size_t)MTOK*DMODEL];
__device__ __half g_uph [(size_t)MTOK*DFF];
__device__ __half g_acth[(size_t)MTOK*DFF];
// fp16 weight copies
__device__ __half g_wip [(size_t)DINPROJ*DMODEL];
__device__ __half g_wop [(size_t)DMODEL*DINNER];
__device__ __half g_wg  [(size_t)DFF*DMODEL];
__device__ __half g_wu  [(size_t)DFF*DMODEL];
__device__ __half g_wd  [(size_t)DMODEL*DFF];

// ------------------------------ helpers ------------------------------------
__device__ __forceinline__ uint32_t smem_u32(const void* p) {
    uint32_t r;
    asm("{ .reg .u64 t; cvta.to.shared.u64 t, %1; cvt.u32.u64 %0, t; }" : "=r"(r) : "l"(p));
    return r;
}
__device__ __forceinline__ void cpa16(uint32_t dst, const void* src, int bytes) {
    asm volatile("cp.async.cg.shared.global [%0], [%1], 16, %2;\n"
                 :: "r"(dst), "l"(src), "r"(bytes));
}
__device__ __forceinline__ void cpa_commit() { asm volatile("cp.async.commit_group;\n"); }
__device__ __forceinline__ void cpa_wait0()  { asm volatile("cp.async.wait_group 0;\n"); }
__device__ __forceinline__ void cpa_wait1()  { asm volatile("cp.async.wait_group 1;\n"); }

#define LDSM4(r0, r1, r2, r3, addr) \
    asm volatile("ldmatrix.sync.aligned.m8n8.x4.shared.b16 {%0,%1,%2,%3}, [%4];" \
        : "=r"(r0), "=r"(r1), "=r"(r2), "=r"(r3) : "r"(addr))

__device__ __forceinline__ float siluf(float g) { return g / (1.f + expf(-g)); }

// fp32 -> fp16 weight conversion (float4 -> 4 halves)
__global__ void w2h_kernel(const float* __restrict__ in, __half* __restrict__ out, int n4) {
    int i = blockIdx.x * blockDim.x + threadIdx.x;
    if (i < n4) {
        float4 v = ((const float4*)in)[i];
        __half2 h0 = __floats2half2_rn(v.x, v.y);
        __half2 h1 = __floats2half2_rn(v.z, v.w);
        uint2 st;
        st.x = *(uint32_t*)&h0;
        st.y = *(uint32_t*)&h1;
        ((uint2*)out)[i] = st;
    }
}

// ------------------------------ rmsnorm (fp16 output) -----------------------
__global__ void rmsnorm_kernel(const float* __restrict__ x, const float* __restrict__ w,
                               __half* __restrict__ y) {
    int row = blockIdx.x;
    const float* xr = x + (size_t)row * DMODEL;
    float ss = 0.f;
    for (int c = threadIdx.x; c < DMODEL; c += 256) { float v = xr[c]; ss += v * v; }
    #pragma unroll
    for (int off = 16; off; off >>= 1) ss += __shfl_xor_sync(0xffffffffu, ss, off);
    __shared__ float red[8];
    if ((threadIdx.x & 31) == 0) red[threadIdx.x >> 5] = ss;
    __syncthreads();
    if (threadIdx.x < 8) {
        float v = red[threadIdx.x];
        #pragma unroll
        for (int off = 4; off; off >>= 1) v += __shfl_xor_sync(0xffu, v, off);
        if (threadIdx.x == 0) red[0] = v;
    }
    __syncthreads();
    float inv = rsqrtf(red[0] / (float)DMODEL + 1e-5f);
    __half* yr = y + (size_t)row * DMODEL;
    for (int c = threadIdx.x; c < DMODEL; c += 256)
        yr[c] = __float2half_rn(w[c] * xr[c] * inv);
}

// ------------------------------ FP16 tensor-core GEMM -----------------------
// acc(fp32) = A(fp16) * W(fp16)^T. A:[M,K], W:[N,K] row-major.
// Epilogue: +res (fp32, opt); silu(acc)*upg (fp16, opt); store C (fp32) and/or
// Ch (fp16). CTA tile 128x256, BK=64, 8 warps of 64x64, mma.m16n8k16,
// ldmatrix, 3-stage cp.async pipeline (round-13 proven config).
#define HROW 144                 // bytes per smem row (64 halves + 8 pad)
#define ASTGB (128 * HROW)       // A stage bytes  (18432)
#define BSTGB (256 * HROW)       // B stage bytes  (36864)
#define STGB  (ASTGB + BSTGB)    // 55296
#define SMEM_HGEMM (3 * STGB)    // 165888

__global__ __launch_bounds__(256, 1) void hgemm_kernel(
        const __half* __restrict__ A, const __half* __restrict__ W,
        const float* __restrict__ res, const __half* __restrict__ upg,
        float* __restrict__ C, __half* __restrict__ Ch,
        int M, int N, int K) {
    extern __shared__ char smraw[];
    const uint32_t sb = smem_u32(smraw);

    int tid = threadIdx.x;
    int bm = blockIdx.y * 128, bn = blockIdx.x * 256;
    int lane = tid & 31, warp = tid >> 5;
    int wm = (warp >> 2) * 64;       // 0 or 64
    int wn = (warp & 3) * 64;        // 0..192
    int grp = lane >> 2, tig = lane & 3;

    // ldmatrix per-lane address components (mat = lane>>3, r = lane&7)
    int mat = lane >> 3, r = lane & 7;
    uint32_t a_off = (uint32_t)(((mat & 1) * 8 + r) * HROW + (mat >> 1) * 16);
    uint32_t b_off = (uint32_t)(((mat >> 1) * 8 + r) * HROW + (mat & 1) * 16);

    float c[4][8][4];
    #pragma unroll
    for (int mt = 0; mt < 4; mt++)
        #pragma unroll
        for (int nt = 0; nt < 8; nt++)
            #pragma unroll
            for (int e = 0; e < 4; e++) c[mt][nt][e] = 0.f;

    const int ldrow = tid >> 3;        // 0..31
    const int c16   = tid & 7;         // 16B chunk (8 halves)

    auto load_tile = [&](int t, int which) {
        int kb = t * 64;
        uint32_t ab = sb + (uint32_t)which * STGB;
        uint32_t wb = ab + ASTGB;
        #pragma unroll
        for (int i = 0; i < 4; i++) {          // A: 128 rows
            int row = ldrow + i * 32;
            cpa16(ab + row * HROW + c16 * 16,
                  A + (size_t)(bm + row) * K + kb + c16 * 8, 16);
        }
        #pragma unroll
        for (int i = 0; i < 8; i++) {          // B: 256 rows
            int row = ldrow + i * 32;
            int n = bn + row;
            int nn = n < N ? n : (N - 1);
            cpa16(wb + row * HROW + c16 * 16,
                  W + (size_t)nn * K + kb + c16 * 8, n < N ? 16 : 0);
        }
    };

    int ntiles = K / 64;
    load_tile(0, 0); cpa_commit();
    load_tile(1, 1); cpa_commit();

    for (int t = 0; t < ntiles; t++) {
        int buf = t % 3;
        if (t + 1 < ntiles) cpa_wait1(); else cpa_wait0();
        __syncthreads();
        if (t + 2 < ntiles) { load_tile(t + 2, (t + 2) % 3); cpa_commit(); }
        uint32_t ab = sb + (uint32_t)buf * STGB;
        uint32_t wb = ab + ASTGB;
        uint32_t abase = ab + (uint32_t)wm * HROW + a_off;
        uint32_t bbase = wb + (uint32_t)wn * HROW + b_off;
        #pragma unroll
        for (int ks = 0; ks < 4; ks++) {
            uint32_t kbyte = (uint32_t)ks * 32;   // 16 halves
            uint32_t af[4][4], bf[8][2];
            #pragma unroll
            for (int mt = 0; mt < 4; mt++)
                LDSM4(af[mt][0], af[mt][1], af[mt][2], af[mt][3],
                      abase + (uint32_t)mt * 16 * HROW + kbyte);
            #pragma unroll
            for (int ntp = 0; ntp < 4; ntp++)
                LDSM4(bf[2*ntp][0], bf[2*ntp][1], bf[2*ntp+1][0], bf[2*ntp+1][1],
                      bbase + (uint32_t)ntp * 16 * HROW + kbyte);
            #pragma unroll
            for (int mt = 0; mt < 4; mt++)
                #pragma unroll
                for (int nt = 0; nt < 8; nt++) {
                    asm volatile(
                        "mma.sync.aligned.m16n8k16.row.col.f32.f16.f16.f32 "
                        "{%0,%1,%2,%3}, {%4,%5,%6,%7}, {%8,%9}, {%0,%1,%2,%3};\n"
                        : "+f"(c[mt][nt][0]), "+f"(c[mt][nt][1]),
                          "+f"(c[mt][nt][2]), "+f"(c[mt][nt][3])
                        : "r"(af[mt][0]), "r"(af[mt][1]), "r"(af[mt][2]), "r"(af[mt][3]),
                          "r"(bf[nt][0]), "r"(bf[nt][1]));
                }
        }
        __syncthreads();
    }

    // epilogue (uniform branches)
    #pragma unroll
    for (int mt = 0; mt < 4; mt++) {
        int r0 = bm + wm + mt * 16 + grp;
        #pragma unroll
        for (int nt = 0; nt < 8; nt++) {
            int col = bn + wn + nt * 8 + 2 * tig;
            if (col < N) {
                float v0 = c[mt][nt][0], v1 = c[mt][nt][1];
                float v2 = c[mt][nt][2], v3 = c[mt][nt][3];
                size_t o0 = (size_t)r0 * N + col;
                size_t o1 = (size_t)(r0 + 8) * N + col;
                if (res) {
                    v0 += res[o0]; v1 += res[o0 + 1];
                    v2 += res[o1]; v3 += res[o1 + 1];
                }
                if (upg) {
                    __half2 u0 = *(const __half2*)(upg + o0);
                    __half2 u1 = *(const __half2*)(upg + o1);
                    v0 = siluf(v0) * __half2float(u0.x);
                    v1 = siluf(v1) * __half2float(u0.y);
                    v2 = siluf(v2) * __half2float(u1.x);
                    v3 = siluf(v3) * __half2float(u1.y);
                }
                if (C) {
                    *(float2*)(C + o0) = make_float2(v0, v1);
                    *(float2*)(C + o1) = make_float2(v2, v3);
                }
                if (Ch) {
                    *(__half2*)(Ch + o0) = __floats2half2_rn(v0, v1);
                    *(__half2*)(Ch + o1) = __floats2half2_rn(v2, v3);
                }
            }
        }
    }
}

// ------------------------------ causal depthwise conv (fp16 out) ------------
__global__ void conv1d_kernel(const float* __restrict__ zx, const float* __restrict__ cw,
                              const float* __restrict__ cb, __half* __restrict__ xBC) {
    size_t idx = (size_t)blockIdx.x * blockDim.x + threadIdx.x;
    if (idx >= (size_t)MTOK * CONVD) return;
    int c = (int)(idx % CONVD);
    int m = (int)(idx / CONVD);
    int t = m & (LSEQ - 1);
    float acc = cb[c];
    #pragma unroll
    for (int j = 0; j < 4; j++) {
        int tt = t - 3 + j;
        if (tt >= 0)
            acc += cw[c * 4 + j] * zx[(size_t)(m - 3 + j) * DINPROJ + DINNER + c];
    }
    xBC[idx] = __float2half_rn(acc);
}

// ------------------------------ SSD intra-chunk (512 threads) ---------------
__global__ void ssd_intra_kernel(const float* __restrict__ zx, const __half* __restrict__ xBC,
                                 float* __restrict__ y, float* __restrict__ Sg,
                                 float* __restrict__ Ag, float* __restrict__ cumg) {
    extern __shared__ float sm[];
    float* xs   = sm;                       // 128*65
    float* Bs   = xs + CHUNK * 65;          // 128*65
    float* Cs   = Bs + CHUNK * 65;          // 128*65
    float* sc   = Cs + CHUNK * 65;          // 128*129
    float* cum  = sc + CHUNK * 129;         // 128
    float* dend = cum + CHUNK;              // 128

    int h = blockIdx.x % NH;
    int c = (blockIdx.x / NH) % NCHUNK;
    int b = blockIdx.x / (NH * NCHUNK);
    int tid = threadIdx.x;
    int m0 = b * LSEQ + c * CHUNK;

    for (int idx = tid; idx < CHUNK * HD; idx += 512) {
        int i = idx >> 6, p = idx & 63;
        size_t rowb = (size_t)(m0 + i) * CONVD;
        xs[i * 65 + p] = __half2float(xBC[rowb + h * HD + p]);
        Bs[i * 65 + p] = __half2float(xBC[rowb + DINNER + h * DSTATE + p]);
        Cs[i * 65 + p] = __half2float(xBC[rowb + DINNER + NH * DSTATE + h * DSTATE + p]);
    }
    if (tid < CHUNK) {
        float d = zx[(size_t)(m0 + tid) * DINPROJ + DTOFF + h];
        float sp = (d > 20.f) ? d : log1pf(expf(d));
        cum[tid] = -sp;
    }
    __syncthreads();
    for (int off = 1; off < CHUNK; off <<= 1) {
        float v = 0.f;
        if (tid < CHUNK && tid >= off) v = cum[tid - off];
        __syncthreads();
        if (tid < CHUNK && tid >= off) cum[tid] += v;
        __syncthreads();
    }
    if (tid < CHUNK) dend[tid] = expf(cum[CHUNK - 1] - cum[tid]);
    __syncthreads();

    // Phase A: sc[i][j] = exp(cum_i - cum_j) * dot(C_i, B_j)
    {
        int ty = tid >> 4;          // 0..31
        int tx = tid & 15;
        int i0 = ty * 4;
        float acc[4][8];
        #pragma unroll
        for (int rr = 0; rr < 4; rr++)
            #pragma unroll
            for (int s = 0; s < 8; s++) acc[rr][s] = 0.f;
        for (int n = 0; n < DSTATE; n++) {
            float cf[4], bf[8];
            #pragma unroll
            for (int rr = 0; rr < 4; rr++) cf[rr] = Cs[(i0 + rr) * 65 + n];
            #pragma unroll
            for (int s = 0; s < 8; s++) bf[s] = Bs[(tx + 16 * s) * 65 + n];
            #pragma unroll
            for (int rr = 0; rr < 4; rr++)
                #pragma unroll
                for (int s = 0; s < 8; s++) acc[rr][s] += cf[rr] * bf[s];
        }
        #pragma unroll
        for (int rr = 0; rr < 4; rr++) {
            int i = i0 + rr;
            float ci = cum[i];
            #pragma unroll
            for (int s = 0; s < 8; s++) {
                int j = tx + 16 * s;
                sc[i * 129 + j] = (j <= i) ? expf(ci - cum[j]) * acc[rr][s] : 0.f;
            }
        }
    }
    __syncthreads();
    // Phase B: y_intra = sc @ x
    {
        int i0 = (tid >> 4) * 4;
        int p0 = (tid & 15) * 4;
        float acc[4][4];
        #pragma unroll
        for (int rr = 0; rr < 4; rr++)
            #pragma unroll
            for (int cc = 0; cc < 4; cc++) acc[rr][cc] = 0.f;
        for (int j = 0; j < CHUNK; j++) {
            float xv[4];
            #pragma unroll
            for (int cc = 0; cc < 4; cc++) xv[cc] = xs[j * 65 + p0 + cc];
            #pragma unroll
            for (int rr = 0; rr < 4; rr++) {
                float sf = sc[(i0 + rr) * 129 + j];
                #pragma unroll
                for (int cc = 0; cc < 4; cc++) acc[rr][cc] += sf * xv[cc];
            }
        }
        #pragma unroll
        for (int rr = 0; rr < 4; rr++) {
            size_t ybase = (size_t)(m0 + i0 + rr) * DINNER + h * HD + p0;
            #pragma unroll
            for (int cc = 0; cc < 4; cc++) y[ybase + cc] = acc[rr][cc];
        }
    }
    // Phase C: chunk state S[n][p] = sum_j dend[j]*B[j,n]*x[j,p]
    {
        int n = tid >> 3;            // 0..63
        int p0 = (tid & 7) * 8;
        float acc[8];
        #pragma unroll
        for (int cc = 0; cc < 8; cc++) acc[cc] = 0.f;
        for (int j = 0; j < CHUNK; j++) {
            float w = dend[j] * Bs[j * 65 + n];
            #pragma unroll
            for (int cc = 0; cc < 8; cc++) acc[cc] += w * xs[j * 65 + p0 + cc];
        }
        size_t off = ((size_t)((b * NCHUNK + c) * NH + h)) * (DSTATE * HD) + n * HD + p0;
        #pragma unroll
        for (int cc = 0; cc < 8; cc++) Sg[off + cc] = acc[cc];
        if (tid == 0) Ag[(b * NCHUNK + c) * NH + h] = expf(cum[CHUNK - 1]);
    }
    if (tid < CHUNK)
        cumg[((size_t)((b * NCHUNK + c) * NH + h)) * CHUNK + tid] = cum[tid];
}

// ------------------------------ inter-chunk state recurrence ----------------
__global__ void state_scan_kernel(const float* __restrict__ Sg, const float* __restrict__ Ag,
                                  float* __restrict__ Hp) {
    int b = blockIdx.x / NH, h = blockIdx.x % NH;
    int tid = threadIdx.x;
    float H[16];
    #pragma unroll
    for (int k = 0; k < 16; k++) H[k] = 0.f;
    for (int c = 0; c < NCHUNK; c++) {
        size_t off = ((size_t)((b * NCHUNK + c) * NH + h)) * (DSTATE * HD);
        float Ac = Ag[(b * NCHUNK + c) * NH + h];
        #pragma unroll
        for (int k = 0; k < 16; k++) {
            int e = tid + k * 256;
            Hp[off + e] = H[k];
            H[k] = Ac * H[k] + Sg[off + e];
        }
    }
}

// ------------------------------ y_inter + D*x + gating (512 thr, fp16 out) --
__global__ void y_inter_kernel(const float* __restrict__ zx, const __half* __restrict__ xBC,
                               const float* __restrict__ Hp, const float* __restrict__ cumg,
                               const float* __restrict__ Dvec, const float* __restrict__ zb,
                               const float* __restrict__ y, __half* __restrict__ yh) {
    extern __shared__ float sm[];
    float* Cs  = sm;                  // 128*65
    float* xs  = Cs + CHUNK * 65;     // 128*65
    float* Hs  = xs + CHUNK * 65;     // 64*65
    float* cum = Hs + DSTATE * 65;    // 128

    int h = blockIdx.x % NH;
    int c = (blockIdx.x / NH) % NCHUNK;
    int b = blockIdx.x / (NH * NCHUNK);
    int tid = threadIdx.x;
    int m0 = b * LSEQ + c * CHUNK;
    size_t hoff = (size_t)((b * NCHUNK + c) * NH + h);

    for (int idx = tid; idx < CHUNK * HD; idx += 512) {
        int i = idx >> 6, p = idx & 63;
        size_t rowb = (size_t)(m0 + i) * CONVD;
        xs[i * 65 + p] = __half2float(xBC[rowb + h * HD + p]);
        Cs[i * 65 + p] = __half2float(xBC[rowb + DINNER + NH * DSTATE + h * DSTATE + p]);
    }
    for (int idx = tid; idx < DSTATE * HD; idx += 512)
        Hs[(idx >> 6) * 65 + (idx & 63)] = Hp[hoff * (DSTATE * HD) + idx];
    if (tid < CHUNK) cum[tid] = cumg[hoff * CHUNK + tid];
    __syncthreads();

    int i = tid >> 2;                 // 0..127
    int p0 = (tid & 3) * 16;
    float acc[16];
    #pragma unroll
    for (int cc = 0; cc < 16; cc++) acc[cc] = 0.f;
    for (int n = 0; n < DSTATE; n++) {
        float cv = Cs[i * 65 + n];
        #pragma unroll
        for (int cc = 0; cc < 16; cc++) acc[cc] += cv * Hs[n * 65 + p0 + cc];
    }
    float e = expf(cum[i]);
    float Dh = Dvec[h];
    int m = m0 + i;
    size_t ybase = (size_t)m * DINNER + h * HD;
    size_t zbase = (size_t)m * DINPROJ + h * HD;
    #pragma unroll
    for (int cc = 0; cc < 16; cc++) {
        int p = p0 + cc;
        float yt = y[ybase + p] + e * acc[cc] + Dh * xs[i * 65 + p];
        float g = zx[zbase + p] + zb[h * HD + p];
        float sg = g / (1.f + expf(-g));
        yh[ybase + p] = __float2half_rn(yt * sg);
    }
}

// ------------------------------ launch --------------------------------------
extern "C" void kernel_launch(void* const* d_in, const int* in_sizes, int n_in,
                              void* d_out, int out_size) {
    const float* hidden     = (const float*)d_in[0];
    const float* in_proj_w  = (const float*)d_in[1];
    const float* z_bias     = (const float*)d_in[2];
    const float* conv_w     = (const float*)d_in[3];
    const float* conv_b     = (const float*)d_in[4];
    const float* Dvec       = (const float*)d_in[5];
    const float* out_proj_w = (const float*)d_in[6];
    const float* norm1_w    = (const float*)d_in[7];
    const float* norm2_w    = (const float*)d_in[8];
    const float* gate_w     = (const float*)d_in[9];
    const float* up_w       = (const float*)d_in[10];
    const float* down_w     = (const float*)d_in[11];
    float* out = (float*)d_out;

    float *zx, *y, *S, *A, *cumg, *Hp, *h2;
    __half *xbc, *h1h, *yh, *h3h, *uph, *acth, *wip, *wop, *wg, *wu, *wd;
    cudaGetSymbolAddress((void**)&zx,   g_zx);
    cudaGetSymbolAddress((void**)&xbc,  g_xBC);
    cudaGetSymbolAddress((void**)&y,    g_y);
    cudaGetSymbolAddress((void**)&S,    g_S);
    cudaGetSymbolAddress((void**)&A,    g_Ac);
    cudaGetSymbolAddress((void**)&cumg, g_cum);
    cudaGetSymbolAddress((void**)&Hp,   g_Hp);
    cudaGetSymbolAddress((void**)&h2,   g_h2);
    cudaGetSymbolAddress((void**)&h1h,  g_h1h);
    cudaGetSymbolAddress((void**)&yh,   g_yh);
    cudaGetSymbolAddress((void**)&h3h,  g_h3h);
    cudaGetSymbolAddress((void**)&uph,  g_uph);
    cudaGetSymbolAddress((void**)&acth, g_acth);
    cudaGetSymbolAddress((void**)&wip,  g_wip);
    cudaGetSymbolAddress((void**)&wop,  g_wop);
    cudaGetSymbolAddress((void**)&wg,   g_wg);
    cudaGetSymbolAddress((void**)&wu,   g_wu);
    cudaGetSymbolAddress((void**)&wd,   g_wd);

    const int SMEM_INTRA  = (3 * CHUNK * 65 + CHUNK * 129 + 2 * CHUNK) * sizeof(float);
    const int SMEM_YINTER = (2 * CHUNK * 65 + DSTATE * 65 + CHUNK) * sizeof(float);
    cudaFuncSetAttribute(ssd_intra_kernel, cudaFuncAttributeMaxDynamicSharedMemorySize, SMEM_INTRA);
    cudaFuncSetAttribute(y_inter_kernel,  cudaFuncAttributeMaxDynamicSharedMemorySize, SMEM_YINTER);
    cudaFuncSetAttribute(hgemm_kernel,    cudaFuncAttributeMaxDynamicSharedMemorySize, SMEM_HGEMM);

    // 0) convert weights fp32 -> fp16
    {
        auto cc = [&](const float* src, __half* dst, size_t n) {
            int n4 = (int)(n / 4);
            w2h_kernel<<<(n4 + 255) / 256, 256>>>(src, dst, n4);
        };
        cc(in_proj_w,  wip, (size_t)DINPROJ * DMODEL);
        cc(out_proj_w, wop, (size_t)DMODEL * DINNER);
        cc(gate_w,     wg,  (size_t)DFF * DMODEL);
        cc(up_w,       wu,  (size_t)DFF * DMODEL);
        cc(down_w,     wd,  (size_t)DMODEL * DFF);
    }

    // 1) rmsnorm 1 -> fp16
    rmsnorm_kernel<<<MTOK, 256>>>(hidden, norm1_w, h1h);
    // 2) in_proj: zx(fp32) = h1 @ in_proj_w^T   [4096 x 8224]
    hgemm_kernel<<<dim3((DINPROJ + 255) / 256, MTOK / 128), 256, SMEM_HGEMM>>>(
        h1h, wip, nullptr, nullptr, zx, nullptr, MTOK, DINPROJ, DMODEL);
    // 3) causal depthwise conv -> fp16 xBC
    conv1d_kernel<<<(int)(((size_t)MTOK * CONVD + 255) / 256), 256>>>(zx, conv_w, conv_b, xbc);
    // 4) SSD intra-chunk (512 threads)
    ssd_intra_kernel<<<BATCH * NCHUNK * NH, 512, SMEM_INTRA>>>(zx, xbc, y, S, A, cumg);
    // 5) inter-chunk state recurrence
    state_scan_kernel<<<BATCH * NH, 256>>>(S, A, Hp);
    // 6) y_inter + D*x + gating -> fp16 (512 threads)
    y_inter_kernel<<<BATCH * NCHUNK * NH, 512, SMEM_YINTER>>>(
        zx, xbc, Hp, cumg, Dvec, z_bias, y, yh);
    // 7) out_proj + residual: h2(fp32) = y @ out_proj_w^T + hidden
    hgemm_kernel<<<dim3(DMODEL / 256, MTOK / 128), 256, SMEM_HGEMM>>>(
        yh, wop, hidden, nullptr, h2, nullptr, MTOK, DMODEL, DINNER);
    // 8) rmsnorm 2 -> fp16
    rmsnorm_kernel<<<MTOK, 256>>>(h2, norm2_w, h3h);
    // 9) up GEMM -> fp16 uph, then gate GEMM with fused silu*up -> fp16 acth
    hgemm_kernel<<<dim3(DFF / 256, MTOK / 128), 256, SMEM_HGEMM>>>(
        h3h, wu, nullptr, nullptr, nullptr, uph, MTOK, DFF, DMODEL);
    hgemm_kernel<<<dim3(DFF / 256, MTOK / 128), 256, SMEM_HGEMM>>>(
        h3h, wg, nullptr, uph, nullptr, acth, MTOK, DFF, DMODEL);
    // 10) down + residual: out = act @ down_w^T + h2
    hgemm_kernel<<<dim3(DMODEL / 256, MTOK / 128), 256, SMEM_HGEMM>>>(
        acth, wd, h2, nullptr, out, nullptr, MTOK, DMODEL, DFF);
}

// round 16
// speedup vs baseline: 1.1725x; 1.1128x over previous
#include <cuda_runtime.h>
#include <cuda_fp16.h>
#include <math.h>
#include <stdint.h>

#define BATCH   2
#define LSEQ    2048
#define MTOK    (BATCH*LSEQ)          // 4096
#define DMODEL  2048
#define DINNER  2048
#define NH      32
#define DSTATE  64
#define HD      64
#define CHUNK   128
#define NCHUNK  (LSEQ/CHUNK)          // 16
#define DFF     8192
#define CONVD   (DINNER + 2*NH*DSTATE)          // 6144
#define DINPROJ (2*DINNER + 2*NH*DSTATE + NH)   // 8224
#define DTOFF   (DINNER + CONVD)                // 8192

// ------------------------- scratch (device globals, no allocs) -------------
__device__ float  g_zx  [(size_t)MTOK*DINPROJ];
__device__ __half g_xBC [(size_t)MTOK*CONVD];
__device__ float  g_y   [(size_t)MTOK*DINNER];
__device__ float  g_S   [(size_t)BATCH*NCHUNK*NH*DSTATE*HD];
__device__ float  g_Ac  [(size_t)BATCH*NCHUNK*NH];
__device__ float  g_cum [(size_t)BATCH*NCHUNK*NH*CHUNK];
__device__ float  g_Hp  [(size_t)BATCH*NCHUNK*NH*DSTATE*HD];
__device__ float  g_h2  [(size_t)MTOK*DMODEL];
// fp16 GEMM activation inputs / intermediates
__device__ __half g_h1h [(size_t)MTOK*DMODEL];
__device__ __half g_yh  [(size_t)MTOK*DINNER];
__device__ __half g_h3h [(size_t)MTOK*DMODEL];
__device__ __half g_uph [(size_t)MTOK*DFF];
__device__ __half g_acth[(size_t)MTOK*DFF];
// fp16 weight copies
__device__ __half g_wip [(size_t)DINPROJ*DMODEL];
__device__ __half g_wop [(size_t)DMODEL*DINNER];
__device__ __half g_wg  [(size_t)DFF*DMODEL];
__device__ __half g_wu  [(size_t)DFF*DMODEL];
__device__ __half g_wd  [(size_t)DMODEL*DFF];

// ------------------------------ helpers ------------------------------------
__device__ __forceinline__ uint32_t smem_u32(const void* p) {
    uint32_t r;
    asm("{ .reg .u64 t; cvta.to.shared.u64 t, %1; cvt.u32.u64 %0, t; }" : "=r"(r) : "l"(p));
    return r;
}
__device__ __forceinline__ void cpa16(uint32_t dst, const void* src, int bytes) {
    asm volatile("cp.async.cg.shared.global [%0], [%1], 16, %2;\n"
                 :: "r"(dst), "l"(src), "r"(bytes));
}
__device__ __forceinline__ void cpa_commit() { asm volatile("cp.async.commit_group;\n"); }
__device__ __forceinline__ void cpa_wait0()  { asm volatile("cp.async.wait_group 0;\n"); }
__device__ __forceinline__ void cpa_wait1()  { asm volatile("cp.async.wait_group 1;\n"); }

#define LDSM4(r0, r1, r2, r3, addr) \
    asm volatile("ldmatrix.sync.aligned.m8n8.x4.shared.b16 {%0,%1,%2,%3}, [%4];" \
        : "=r"(r0), "=r"(r1), "=r"(r2), "=r"(r3) : "r"(addr))

#define HMMA(c0, c1, c2, c3, a0, a1, a2, a3, b0, b1) \
    asm volatile( \
        "mma.sync.aligned.m16n8k16.row.col.f32.f16.f16.f32 " \
        "{%0,%1,%2,%3}, {%4,%5,%6,%7}, {%8,%9}, {%0,%1,%2,%3};\n" \
        : "+f"(c0), "+f"(c1), "+f"(c2), "+f"(c3) \
        : "r"(a0), "r"(a1), "r"(a2), "r"(a3), "r"(b0), "r"(b1))

__device__ __forceinline__ float siluf(float g) { return g / (1.f + expf(-g)); }

// fp32 -> fp16 weight conversion (float4 -> 4 halves)
__global__ void w2h_kernel(const float* __restrict__ in, __half* __restrict__ out, int n4) {
    int i = blockIdx.x * blockDim.x + threadIdx.x;
    if (i < n4) {
        float4 v = ((const float4*)in)[i];
        __half2 h0 = __floats2half2_rn(v.x, v.y);
        __half2 h1 = __floats2half2_rn(v.z, v.w);
        uint2 st;
        st.x = *(uint32_t*)&h0;
        st.y = *(uint32_t*)&h1;
        ((uint2*)out)[i] = st;
    }
}

// ------------------------------ rmsnorm (fp16 output) -----------------------
__global__ void rmsnorm_kernel(const float* __restrict__ x, const float* __restrict__ w,
                               __half* __restrict__ y) {
    int row = blockIdx.x;
    const float* xr = x + (size_t)row * DMODEL;
    float ss = 0.f;
    for (int c = threadIdx.x; c < DMODEL; c += 256) { float v = xr[c]; ss += v * v; }
    #pragma unroll
    for (int off = 16; off; off >>= 1) ss += __shfl_xor_sync(0xffffffffu, ss, off);
    __shared__ float red[8];
    if ((threadIdx.x & 31) == 0) red[threadIdx.x >> 5] = ss;
    __syncthreads();
    if (threadIdx.x < 8) {
        float v = red[threadIdx.x];
        #pragma unroll
        for (int off = 4; off; off >>= 1) v += __shfl_xor_sync(0xffu, v, off);
        if (threadIdx.x == 0) red[0] = v;
    }
    __syncthreads();
    float inv = rsqrtf(red[0] / (float)DMODEL + 1e-5f);
    __half* yr = y + (size_t)row * DMODEL;
    for (int c = threadIdx.x; c < DMODEL; c += 256)
        yr[c] = __float2half_rn(w[c] * xr[c] * inv);
}

// ------------------------------ FP16 tensor-core GEMM -----------------------
// acc(fp32) = A(fp16) * W(fp16)^T. Epilogue: +res / silu*upg / fp32+fp16 out.
// CTA 128x256, BK=64, 8 warps of 64x64, 3-stage cp.async (round-13/15 proven).
#define HROW 144                 // bytes per smem row (64 halves + 8 pad)
#define ASTGB (128 * HROW)
#define BSTGB (256 * HROW)
#define STGB  (ASTGB + BSTGB)
#define SMEM_HGEMM (3 * STGB)

__global__ __launch_bounds__(256, 1) void hgemm_kernel(
        const __half* __restrict__ A, const __half* __restrict__ W,
        const float* __restrict__ res, const __half* __restrict__ upg,
        float* __restrict__ C, __half* __restrict__ Ch,
        int M, int N, int K) {
    extern __shared__ char smraw[];
    const uint32_t sb = smem_u32(smraw);

    int tid = threadIdx.x;
    int bm = blockIdx.y * 128, bn = blockIdx.x * 256;
    int lane = tid & 31, warp = tid >> 5;
    int wm = (warp >> 2) * 64;
    int wn = (warp & 3) * 64;
    int grp = lane >> 2, tig = lane & 3;

    int mat = lane >> 3, r = lane & 7;
    uint32_t a_off = (uint32_t)(((mat & 1) * 8 + r) * HROW + (mat >> 1) * 16);
    uint32_t b_off = (uint32_t)(((mat >> 1) * 8 + r) * HROW + (mat & 1) * 16);

    float c[4][8][4];
    #pragma unroll
    for (int mt = 0; mt < 4; mt++)
        #pragma unroll
        for (int nt = 0; nt < 8; nt++)
            #pragma unroll
            for (int e = 0; e < 4; e++) c[mt][nt][e] = 0.f;

    const int ldrow = tid >> 3;
    const int c16   = tid & 7;

    auto load_tile = [&](int t, int which) {
        int kb = t * 64;
        uint32_t ab = sb + (uint32_t)which * STGB;
        uint32_t wb = ab + ASTGB;
        #pragma unroll
        for (int i = 0; i < 4; i++) {
            int row = ldrow + i * 32;
            cpa16(ab + row * HROW + c16 * 16,
                  A + (size_t)(bm + row) * K + kb + c16 * 8, 16);
        }
        #pragma unroll
        for (int i = 0; i < 8; i++) {
            int row = ldrow + i * 32;
            int n = bn + row;
            int nn = n < N ? n : (N - 1);
            cpa16(wb + row * HROW + c16 * 16,
                  W + (size_t)nn * K + kb + c16 * 8, n < N ? 16 : 0);
        }
    };

    int ntiles = K / 64;
    load_tile(0, 0); cpa_commit();
    load_tile(1, 1); cpa_commit();

    for (int t = 0; t < ntiles; t++) {
        int buf = t % 3;
        if (t + 1 < ntiles) cpa_wait1(); else cpa_wait0();
        __syncthreads();
        if (t + 2 < ntiles) { load_tile(t + 2, (t + 2) % 3); cpa_commit(); }
        uint32_t ab = sb + (uint32_t)buf * STGB;
        uint32_t wb = ab + ASTGB;
        uint32_t abase = ab + (uint32_t)wm * HROW + a_off;
        uint32_t bbase = wb + (uint32_t)wn * HROW + b_off;
        #pragma unroll
        for (int ks = 0; ks < 4; ks++) {
            uint32_t kbyte = (uint32_t)ks * 32;
            uint32_t af[4][4], bf[8][2];
            #pragma unroll
            for (int mt = 0; mt < 4; mt++)
                LDSM4(af[mt][0], af[mt][1], af[mt][2], af[mt][3],
                      abase + (uint32_t)mt * 16 * HROW + kbyte);
            #pragma unroll
            for (int ntp = 0; ntp < 4; ntp++)
                LDSM4(bf[2*ntp][0], bf[2*ntp][1], bf[2*ntp+1][0], bf[2*ntp+1][1],
                      bbase + (uint32_t)ntp * 16 * HROW + kbyte);
            #pragma unroll
            for (int mt = 0; mt < 4; mt++)
                #pragma unroll
                for (int nt = 0; nt < 8; nt++)
                    HMMA(c[mt][nt][0], c[mt][nt][1], c[mt][nt][2], c[mt][nt][3],
                         af[mt][0], af[mt][1], af[mt][2], af[mt][3],
                         bf[nt][0], bf[nt][1]);
        }
        __syncthreads();
    }

    #pragma unroll
    for (int mt = 0; mt < 4; mt++) {
        int r0 = bm + wm + mt * 16 + grp;
        #pragma unroll
        for (int nt = 0; nt < 8; nt++) {
            int col = bn + wn + nt * 8 + 2 * tig;
            if (col < N) {
                float v0 = c[mt][nt][0], v1 = c[mt][nt][1];
                float v2 = c[mt][nt][2], v3 = c[mt][nt][3];
                size_t o0 = (size_t)r0 * N + col;
                size_t o1 = (size_t)(r0 + 8) * N + col;
                if (res) {
                    v0 += res[o0]; v1 += res[o0 + 1];
                    v2 += res[o1]; v3 += res[o1 + 1];
                }
                if (upg) {
                    __half2 u0 = *(const __half2*)(upg + o0);
                    __half2 u1 = *(const __half2*)(upg + o1);
                    v0 = siluf(v0) * __half2float(u0.x);
                    v1 = siluf(v1) * __half2float(u0.y);
                    v2 = siluf(v2) * __half2float(u1.x);
                    v3 = siluf(v3) * __half2float(u1.y);
                }
                if (C) {
                    *(float2*)(C + o0) = make_float2(v0, v1);
                    *(float2*)(C + o1) = make_float2(v2, v3);
                }
                if (Ch) {
                    *(__half2*)(Ch + o0) = __floats2half2_rn(v0, v1);
                    *(__half2*)(Ch + o1) = __floats2half2_rn(v2, v3);
                }
            }
        }
    }
}

// ------------------------------ causal depthwise conv (fp16 out) ------------
__global__ void conv1d_kernel(const float* __restrict__ zx, const float* __restrict__ cw,
                              const float* __restrict__ cb, __half* __restrict__ xBC) {
    size_t idx = (size_t)blockIdx.x * blockDim.x + threadIdx.x;
    if (idx >= (size_t)MTOK * CONVD) return;
    int c = (int)(idx % CONVD);
    int m = (int)(idx / CONVD);
    int t = m & (LSEQ - 1);
    float acc = cb[c];
    #pragma unroll
    for (int j = 0; j < 4; j++) {
        int tt = t - 3 + j;
        if (tt >= 0)
            acc += cw[c * 4 + j] * zx[(size_t)(m - 3 + j) * DINPROJ + DINNER + c];
    }
    xBC[idx] = __float2half_rn(acc);
}

// ------------------------------ SSD intra-chunk (tensor-core, 512 thr) ------
// Phase A: sc = mask(exp) .* (C @ B^T)    128x128x64
// Phase B: y_intra = sc @ x               128x64x128 (x via xT, K-contig)
// Phase C: S = (B^T diag(dend)) @ x       64x64x128  (Bd, xT)
#define SROW64  144    // 72 halves/row (64 data + 8 pad)
#define SROW128 272    // 136 halves/row (128 data + 8 pad)
#define SOFF_CS   0
#define SOFF_BS   18432
#define SOFF_XT   36864
#define SOFF_BD   54272
#define SOFF_SC   71680
#define SOFF_CUM  106496
#define SOFF_DEND 107008
#define SMEM_INTRA 107520

__global__ __launch_bounds__(512) void ssd_intra_kernel(
        const float* __restrict__ zx, const __half* __restrict__ xBC,
        float* __restrict__ y, float* __restrict__ Sg,
        float* __restrict__ Ag, float* __restrict__ cumg) {
    extern __shared__ char smraw[];
    const uint32_t sb = smem_u32(smraw);
    __half* Cs = (__half*)(smraw + SOFF_CS);
    __half* Bs = (__half*)(smraw + SOFF_BS);
    __half* xT = (__half*)(smraw + SOFF_XT);
    __half* Bd = (__half*)(smraw + SOFF_BD);
    __half* sc = (__half*)(smraw + SOFF_SC);
    float* cum  = (float*)(smraw + SOFF_CUM);
    float* dend = (float*)(smraw + SOFF_DEND);

    int h = blockIdx.x % NH;
    int c = (blockIdx.x / NH) % NCHUNK;
    int b = blockIdx.x / (NH * NCHUNK);
    int tid = threadIdx.x;
    int lane = tid & 31, warp = tid >> 5;
    int grp = lane >> 2, tig = lane & 3;
    int mat = lane >> 3, r = lane & 7;
    int m0 = b * LSEQ + c * CHUNK;

    // stage C, B (row-major, 72-half rows) and x transposed (xT[p][i])
    for (int idx = tid; idx < CHUNK * 32; idx += 512) {
        int i = idx >> 5, p2 = idx & 31;
        size_t rowb = (size_t)(m0 + i) * CONVD;
        __half2 xv = *(const __half2*)(xBC + rowb + h * HD + 2 * p2);
        __half2 bv = *(const __half2*)(xBC + rowb + DINNER + h * DSTATE + 2 * p2);
        __half2 cv = *(const __half2*)(xBC + rowb + DINNER + NH * DSTATE + h * DSTATE + 2 * p2);
        *(__half2*)(Cs + i * 72 + 2 * p2) = cv;
        *(__half2*)(Bs + i * 72 + 2 * p2) = bv;
        xT[(2 * p2) * 136 + i]     = __low2half(xv);
        xT[(2 * p2 + 1) * 136 + i] = __high2half(xv);
    }
    if (tid < CHUNK) {
        float d = zx[(size_t)(m0 + tid) * DINPROJ + DTOFF + h];
        float sp = (d > 20.f) ? d : log1pf(expf(d));
        cum[tid] = -sp;
    }
    __syncthreads();
    for (int off = 1; off < CHUNK; off <<= 1) {
        float v = 0.f;
        if (tid < CHUNK && tid >= off) v = cum[tid - off];
        __syncthreads();
        if (tid < CHUNK && tid >= off) cum[tid] += v;
        __syncthreads();
    }
    if (tid < CHUNK) dend[tid] = expf(cum[CHUNK - 1] - cum[tid]);
    __syncthreads();

    // Bd[n][j] = B[j][n] * dend[j]
    for (int idx = tid; idx < DSTATE * CHUNK; idx += 512) {
        int n = idx >> 7, j = idx & 127;
        Bd[n * 136 + j] = __float2half_rn(__half2float(Bs[j * 72 + n]) * dend[j]);
    }

    // Phase A: 16 warps, 4x4 grid of 32x32 tiles over sc
    {
        int wr = warp >> 2, wc = warp & 3;
        int i0 = wr * 32, j0 = wc * 32;
        float a[2][4][4];
        #pragma unroll
        for (int mt = 0; mt < 2; mt++)
            #pragma unroll
            for (int nt = 0; nt < 4; nt++)
                #pragma unroll
                for (int e = 0; e < 4; e++) a[mt][nt][e] = 0.f;
        if (wc <= wr) {
            uint32_t abase = sb + SOFF_CS + (uint32_t)(((mat & 1) * 8 + r) * SROW64 + (mat >> 1) * 16)
                           + (uint32_t)i0 * SROW64;
            uint32_t bbase = sb + SOFF_BS + (uint32_t)(((mat >> 1) * 8 + r) * SROW64 + (mat & 1) * 16)
                           + (uint32_t)j0 * SROW64;
            #pragma unroll
            for (int ks = 0; ks < 4; ks++) {
                uint32_t kb = (uint32_t)ks * 32;
                uint32_t af[2][4], bf[4][2];
                LDSM4(af[0][0], af[0][1], af[0][2], af[0][3], abase + kb);
                LDSM4(af[1][0], af[1][1], af[1][2], af[1][3], abase + 16u * SROW64 + kb);
                LDSM4(bf[0][0], bf[0][1], bf[1][0], bf[1][1], bbase + kb);
                LDSM4(bf[2][0], bf[2][1], bf[3][0], bf[3][1], bbase + 16u * SROW64 + kb);
                #pragma unroll
                for (int mt = 0; mt < 2; mt++)
                    #pragma unroll
                    for (int nt = 0; nt < 4; nt++)
                        HMMA(a[mt][nt][0], a[mt][nt][1], a[mt][nt][2], a[mt][nt][3],
                             af[mt][0], af[mt][1], af[mt][2], af[mt][3],
                             bf[nt][0], bf[nt][1]);
            }
        }
        #pragma unroll
        for (int mt = 0; mt < 2; mt++) {
            int i1 = i0 + mt * 16 + grp, i2 = i1 + 8;
            float ci1 = cum[i1], ci2 = cum[i2];
            #pragma unroll
            for (int nt = 0; nt < 4; nt++) {
                int j = j0 + nt * 8 + 2 * tig;
                float cj0 = cum[j], cj1 = cum[j + 1];
                float v0 = (j     <= i1) ? expf(ci1 - cj0) * a[mt][nt][0] : 0.f;
                float v1 = (j + 1 <= i1) ? expf(ci1 - cj1) * a[mt][nt][1] : 0.f;
                float v2 = (j     <= i2) ? expf(ci2 - cj0) * a[mt][nt][2] : 0.f;
                float v3 = (j + 1 <= i2) ? expf(ci2 - cj1) * a[mt][nt][3] : 0.f;
                *(__half2*)(sc + i1 * 136 + j) = __floats2half2_rn(v0, v1);
                *(__half2*)(sc + i2 * 136 + j) = __floats2half2_rn(v2, v3);
            }
        }
    }
    __syncthreads();

    // Phase B: y_intra = sc @ x  (warp tile 32x16, K=128)
    {
        int i0 = (warp >> 2) * 32, p0 = (warp & 3) * 16;
        float acc[2][2][4];
        #pragma unroll
        for (int mt = 0; mt < 2; mt++)
            #pragma unroll
            for (int nt = 0; nt < 2; nt++)
                #pragma unroll
                for (int e = 0; e < 4; e++) acc[mt][nt][e] = 0.f;
        uint32_t abase = sb + SOFF_SC + (uint32_t)(((mat & 1) * 8 + r) * SROW128 + (mat >> 1) * 16)
                       + (uint32_t)i0 * SROW128;
        uint32_t bbase = sb + SOFF_XT + (uint32_t)(((mat >> 1) * 8 + r) * SROW128 + (mat & 1) * 16)
                       + (uint32_t)p0 * SROW128;
        #pragma unroll
        for (int ks = 0; ks < 8; ks++) {
            uint32_t kb = (uint32_t)ks * 32;
            uint32_t af[2][4], bf[2][2];
            LDSM4(af[0][0], af[0][1], af[0][2], af[0][3], abase + kb);
            LDSM4(af[1][0], af[1][1], af[1][2], af[1][3], abase + 16u * SROW128 + kb);
            LDSM4(bf[0][0], bf[0][1], bf[1][0], bf[1][1], bbase + kb);
            #pragma unroll
            for (int mt = 0; mt < 2; mt++)
                #pragma unroll
                for (int nt = 0; nt < 2; nt++)
                    HMMA(acc[mt][nt][0], acc[mt][nt][1], acc[mt][nt][2], acc[mt][nt][3],
                         af[mt][0], af[mt][1], af[mt][2], af[mt][3],
                         bf[nt][0], bf[nt][1]);
        }
        #pragma unroll
        for (int mt = 0; mt < 2; mt++) {
            int i1 = i0 + mt * 16 + grp;
            #pragma unroll
            for (int nt = 0; nt < 2; nt++) {
                int p = p0 + nt * 8 + 2 * tig;
                size_t o0 = (size_t)(m0 + i1) * DINNER + h * HD + p;
                size_t o1 = (size_t)(m0 + i1 + 8) * DINNER + h * HD + p;
                *(float2*)(y + o0) = make_float2(acc[mt][nt][0], acc[mt][nt][1]);
                *(float2*)(y + o1) = make_float2(acc[mt][nt][2], acc[mt][nt][3]);
            }
        }
    }

    // Phase C: S = Bd @ x  (warp tile 16x16, K=128)
    {
        int n0 = (warp >> 2) * 16, p0 = (warp & 3) * 16;
        float acc[2][4];
        #pragma unroll
        for (int nt = 0; nt < 2; nt++)
            #pragma unroll
            for (int e = 0; e < 4; e++) acc[nt][e] = 0.f;
        uint32_t abase = sb + SOFF_BD + (uint32_t)(((mat & 1) * 8 + r) * SROW128 + (mat >> 1) * 16)
                       + (uint32_t)n0 * SROW128;
        uint32_t bbase = sb + SOFF_XT + (uint32_t)(((mat >> 1) * 8 + r) * SROW128 + (mat & 1) * 16)
                       + (uint32_t)p0 * SROW128;
        #pragma unroll
        for (int ks = 0; ks < 8; ks++) {
            uint32_t kb = (uint32_t)ks * 32;
            uint32_t af[4], bf[2][2];
            LDSM4(af[0], af[1], af[2], af[3], abase + kb);
            LDSM4(bf[0][0], bf[0][1], bf[1][0], bf[1][1], bbase + kb);
            #pragma unroll
            for (int nt = 0; nt < 2; nt++)
                HMMA(acc[nt][0], acc[nt][1], acc[nt][2], acc[nt][3],
                     af[0], af[1], af[2], af[3], bf[nt][0], bf[nt][1]);
        }
        size_t off = ((size_t)((b * NCHUNK + c) * NH + h)) * (DSTATE * HD);
        #pragma unroll
        for (int nt = 0; nt < 2; nt++) {
            int p = p0 + nt * 8 + 2 * tig;
            *(float2*)(Sg + off + (n0 + grp) * HD + p)     = make_float2(acc[nt][0], acc[nt][1]);
            *(float2*)(Sg + off + (n0 + grp + 8) * HD + p) = make_float2(acc[nt][2], acc[nt][3]);
        }
    }

    if (tid == 0) Ag[(b * NCHUNK + c) * NH + h] = expf(cum[CHUNK - 1]);
    if (tid < CHUNK)
        cumg[((size_t)((b * NCHUNK + c) * NH + h)) * CHUNK + tid] = cum[tid];
}

// ------------------------------ inter-chunk state recurrence ----------------
__global__ void state_scan_kernel(const float* __restrict__ Sg, const float* __restrict__ Ag,
                                  float* __restrict__ Hp) {
    int b = blockIdx.x / NH, h = blockIdx.x % NH;
    int tid = threadIdx.x;
    float H[16];
    #pragma unroll
    for (int k = 0; k < 16; k++) H[k] = 0.f;
    for (int c = 0; c < NCHUNK; c++) {
        size_t off = ((size_t)((b * NCHUNK + c) * NH + h)) * (DSTATE * HD);
        float Ac = Ag[(b * NCHUNK + c) * NH + h];
        #pragma unroll
        for (int k = 0; k < 16; k++) {
            int e = tid + k * 256;
            Hp[off + e] = H[k];
            H[k] = Ac * H[k] + Sg[off + e];
        }
    }
}

// ------------------------------ y_inter + D*x + gating (512 thr, fp16 out) --
__global__ void y_inter_kernel(const float* __restrict__ zx, const __half* __restrict__ xBC,
                               const float* __restrict__ Hp, const float* __restrict__ cumg,
                               const float* __restrict__ Dvec, const float* __restrict__ zb,
                               const float* __restrict__ y, __half* __restrict__ yh) {
    extern __shared__ float sm[];
    float* Cs  = sm;                  // 128*65
    float* xs  = Cs + CHUNK * 65;     // 128*65
    float* Hs  = xs + CHUNK * 65;     // 64*65
    float* cum = Hs + DSTATE * 65;    // 128

    int h = blockIdx.x % NH;
    int c = (blockIdx.x / NH) % NCHUNK;
    int b = blockIdx.x / (NH * NCHUNK);
    int tid = threadIdx.x;
    int m0 = b * LSEQ + c * CHUNK;
    size_t hoff = (size_t)((b * NCHUNK + c) * NH + h);

    for (int idx = tid; idx < CHUNK * HD; idx += 512) {
        int i = idx >> 6, p = idx & 63;
        size_t rowb = (size_t)(m0 + i) * CONVD;
        xs[i * 65 + p] = __half2float(xBC[rowb + h * HD + p]);
        Cs[i * 65 + p] = __half2float(xBC[rowb + DINNER + NH * DSTATE + h * DSTATE + p]);
    }
    for (int idx = tid; idx < DSTATE * HD; idx += 512)
        Hs[(idx >> 6) * 65 + (idx & 63)] = Hp[hoff * (DSTATE * HD) + idx];
    if (tid < CHUNK) cum[tid] = cumg[hoff * CHUNK + tid];
    __syncthreads();

    int i = tid >> 2;                 // 0..127
    int p0 = (tid & 3) * 16;
    float acc[16];
    #pragma unroll
    for (int cc = 0; cc < 16; cc++) acc[cc] = 0.f;
    for (int n = 0; n < DSTATE; n++) {
        float cv = Cs[i * 65 + n];
        #pragma unroll
        for (int cc = 0; cc < 16; cc++) acc[cc] += cv * Hs[n * 65 + p0 + cc];
    }
    float e = expf(cum[i]);
    float Dh = Dvec[h];
    int m = m0 + i;
    size_t ybase = (size_t)m * DINNER + h * HD;
    size_t zbase = (size_t)m * DINPROJ + h * HD;
    #pragma unroll
    for (int cc = 0; cc < 16; cc++) {
        int p = p0 + cc;
        float yt = y[ybase + p] + e * acc[cc] + Dh * xs[i * 65 + p];
        float g = zx[zbase + p] + zb[h * HD + p];
        float sg = g / (1.f + expf(-g));
        yh[ybase + p] = __float2half_rn(yt * sg);
    }
}

// ------------------------------ launch --------------------------------------
extern "C" void kernel_launch(void* const* d_in, const int* in_sizes, int n_in,
                              void* d_out, int out_size) {
    const float* hidden     = (const float*)d_in[0];
    const float* in_proj_w  = (const float*)d_in[1];
    const float* z_bias     = (const float*)d_in[2];
    const float* conv_w     = (const float*)d_in[3];
    const float* conv_b     = (const float*)d_in[4];
    const float* Dvec       = (const float*)d_in[5];
    const float* out_proj_w = (const float*)d_in[6];
    const float* norm1_w    = (const float*)d_in[7];
    const float* norm2_w    = (const float*)d_in[8];
    const float* gate_w     = (const float*)d_in[9];
    const float* up_w       = (const float*)d_in[10];
    const float* down_w     = (const float*)d_in[11];
    float* out = (float*)d_out;

    float *zx, *y, *S, *A, *cumg, *Hp, *h2;
    __half *xbc, *h1h, *yh, *h3h, *uph, *acth, *wip, *wop, *wg, *wu, *wd;
    cudaGetSymbolAddress((void**)&zx,   g_zx);
    cudaGetSymbolAddress((void**)&xbc,  g_xBC);
    cudaGetSymbolAddress((void**)&y,    g_y);
    cudaGetSymbolAddress((void**)&S,    g_S);
    cudaGetSymbolAddress((void**)&A,    g_Ac);
    cudaGetSymbolAddress((void**)&cumg, g_cum);
    cudaGetSymbolAddress((void**)&Hp,   g_Hp);
    cudaGetSymbolAddress((void**)&h2,   g_h2);
    cudaGetSymbolAddress((void**)&h1h,  g_h1h);
    cudaGetSymbolAddress((void**)&yh,   g_yh);
    cudaGetSymbolAddress((void**)&h3h,  g_h3h);
    cudaGetSymbolAddress((void**)&uph,  g_uph);
    cudaGetSymbolAddress((void**)&acth, g_acth);
    cudaGetSymbolAddress((void**)&wip,  g_wip);
    cudaGetSymbolAddress((void**)&wop,  g_wop);
    cudaGetSymbolAddress((void**)&wg,   g_wg);
    cudaGetSymbolAddress((void**)&wu,   g_wu);
    cudaGetSymbolAddress((void**)&wd,   g_wd);

    const int SMEM_YINTER = (2 * CHUNK * 65 + DSTATE * 65 + CHUNK) * sizeof(float);
    cudaFuncSetAttribute(ssd_intra_kernel, cudaFuncAttributeMaxDynamicSharedMemorySize, SMEM_INTRA);
    cudaFuncSetAttribute(y_inter_kernel,  cudaFuncAttributeMaxDynamicSharedMemorySize, SMEM_YINTER);
    cudaFuncSetAttribute(hgemm_kernel,    cudaFuncAttributeMaxDynamicSharedMemorySize, SMEM_HGEMM);

    // 0) convert weights fp32 -> fp16
    {
        auto cc = [&](const float* src, __half* dst, size_t n) {
            int n4 = (int)(n / 4);
            w2h_kernel<<<(n4 + 255) / 256, 256>>>(src, dst, n4);
        };
        cc(in_proj_w,  wip, (size_t)DINPROJ * DMODEL);
        cc(out_proj_w, wop, (size_t)DMODEL * DINNER);
        cc(gate_w,     wg,  (size_t)DFF * DMODEL);
        cc(up_w,       wu,  (size_t)DFF * DMODEL);
        cc(down_w,     wd,  (size_t)DMODEL * DFF);
    }

    // 1) rmsnorm 1 -> fp16
    rmsnorm_kernel<<<MTOK, 256>>>(hidden, norm1_w, h1h);
    // 2) in_proj: zx(fp32) = h1 @ in_proj_w^T   [4096 x 8224]
    hgemm_kernel<<<dim3((DINPROJ + 255) / 256, MTOK / 128), 256, SMEM_HGEMM>>>(
        h1h, wip, nullptr, nullptr, zx, nullptr, MTOK, DINPROJ, DMODEL);
    // 3) causal depthwise conv -> fp16 xBC
    conv1d_kernel<<<(int)(((size_t)MTOK * CONVD + 255) / 256), 256>>>(zx, conv_w, conv_b, xbc);
    // 4) SSD intra-chunk (tensor-core)
    ssd_intra_kernel<<<BATCH * NCHUNK * NH, 512, SMEM_INTRA>>>(zx, xbc, y, S, A, cumg);
    // 5) inter-chunk state recurrence
    state_scan_kernel<<<BATCH * NH, 256>>>(S, A, Hp);
    // 6) y_inter + D*x + gating -> fp16 (512 threads)
    y_inter_kernel<<<BATCH * NCHUNK * NH, 512, SMEM_YINTER>>>(
        zx, xbc, Hp, cumg, Dvec, z_bias, y, yh);
    // 7) out_proj + residual: h2(fp32) = y @ out_proj_w^T + hidden
    hgemm_kernel<<<dim3(DMODEL / 256, MTOK / 128), 256, SMEM_HGEMM>>>(
        yh, wop, hidden, nullptr, h2, nullptr, MTOK, DMODEL, DINNER);
    // 8) rmsnorm 2 -> fp16
    rmsnorm_kernel<<<MTOK, 256>>>(h2, norm2_w, h3h);
    // 9) up GEMM -> fp16 uph, then gate GEMM with fused silu*up -> fp16 acth
    hgemm_kernel<<<dim3(DFF / 256, MTOK / 128), 256, SMEM_HGEMM>>>(
        h3h, wu, nullptr, nullptr, nullptr, uph, MTOK, DFF, DMODEL);
    hgemm_kernel<<<dim3(DFF / 256, MTOK / 128), 256, SMEM_HGEMM>>>(
        h3h, wg, nullptr, uph, nullptr, acth, MTOK, DFF, DMODEL);
    // 10) down + residual: out = act @ down_w^T + h2
    hgemm_kernel<<<dim3(DMODEL / 256, MTOK / 128), 256, SMEM_HGEMM>>>(
        acth, wd, h2, nullptr, out, MTOK == 0 ? nullptr : nullptr, MTOK, DMODEL, DFF);
}

// round 17
// speedup vs baseline: 1.2519x; 1.0677x over previous
#include <cuda_runtime.h>
#include <cuda_fp16.h>
#include <math.h>
#include <stdint.h>

#define BATCH   2
#define LSEQ    2048
#define MTOK    (BATCH*LSEQ)          // 4096
#define DMODEL  2048
#define DINNER  2048
#define NH      32
#define DSTATE  64
#define HD      64
#define CHUNK   128
#define NCHUNK  (LSEQ/CHUNK)          // 16
#define DFF     8192
#define CONVD   (DINNER + 2*NH*DSTATE)          // 6144
#define DINPROJ (2*DINNER + 2*NH*DSTATE + NH)   // 8224
#define DTOFF   (DINNER + CONVD)                // 8192

// ------------------------- scratch (device globals, no allocs) -------------
__device__ float  g_zx  [(size_t)MTOK*DINPROJ];
__device__ __half g_xBC [(size_t)MTOK*CONVD];
__device__ __half g_yi  [(size_t)MTOK*DINNER];      // y_intra (fp16)
__device__ float  g_S   [(size_t)BATCH*NCHUNK*NH*DSTATE*HD];
__device__ float  g_Ac  [(size_t)BATCH*NCHUNK*NH];
__device__ float  g_cum [(size_t)BATCH*NCHUNK*NH*CHUNK];
__device__ float  g_Hp  [(size_t)BATCH*NCHUNK*NH*DSTATE*HD];
__device__ float  g_h2  [(size_t)MTOK*DMODEL];
// fp16 GEMM activation inputs / intermediates
__device__ __half g_h1h [(size_t)MTOK*DMODEL];
__device__ __half g_yh  [(size_t)MTOK*DINNER];
__device__ __half g_h3h [(size_t)MTOK*DMODEL];
__device__ __half g_uph [(size_t)MTOK*DFF];
__device__ __half g_acth[(size_t)MTOK*DFF];
// fp16 weight copies
__device__ __half g_wip [(size_t)DINPROJ*DMODEL];
__device__ __half g_wop [(size_t)DMODEL*DINNER];
__device__ __half g_wg  [(size_t)DFF*DMODEL];
__device__ __half g_wu  [(size_t)DFF*DMODEL];
__device__ __half g_wd  [(size_t)DMODEL*DFF];

// ------------------------------ helpers ------------------------------------
__device__ __forceinline__ uint32_t smem_u32(const void* p) {
    uint32_t r;
    asm("{ .reg .u64 t; cvta.to.shared.u64 t, %1; cvt.u32.u64 %0, t; }" : "=r"(r) : "l"(p));
    return r;
}
__device__ __forceinline__ void cpa16(uint32_t dst, const void* src, int bytes) {
    asm volatile("cp.async.cg.shared.global [%0], [%1], 16, %2;\n"
                 :: "r"(dst), "l"(src), "r"(bytes));
}
__device__ __forceinline__ void cpa_commit() { asm volatile("cp.async.commit_group;\n"); }
__device__ __forceinline__ void cpa_wait0()  { asm volatile("cp.async.wait_group 0;\n"); }
__device__ __forceinline__ void cpa_wait1()  { asm volatile("cp.async.wait_group 1;\n"); }

#define LDSM4(r0, r1, r2, r3, addr) \
    asm volatile("ldmatrix.sync.aligned.m8n8.x4.shared.b16 {%0,%1,%2,%3}, [%4];" \
        : "=r"(r0), "=r"(r1), "=r"(r2), "=r"(r3) : "r"(addr))

#define HMMA(c0, c1, c2, c3, a0, a1, a2, a3, b0, b1) \
    asm volatile( \
        "mma.sync.aligned.m16n8k16.row.col.f32.f16.f16.f32 " \
        "{%0,%1,%2,%3}, {%4,%5,%6,%7}, {%8,%9}, {%0,%1,%2,%3};\n" \
        : "+f"(c0), "+f"(c1), "+f"(c2), "+f"(c3) \
        : "r"(a0), "r"(a1), "r"(a2), "r"(a3), "r"(b0), "r"(b1))

__device__ __forceinline__ float siluf(float g) { return g / (1.f + expf(-g)); }

// fp32 -> fp16 weight conversion
__global__ void w2h_kernel(const float* __restrict__ in, __half* __restrict__ out, int n4) {
    int i = blockIdx.x * blockDim.x + threadIdx.x;
    if (i < n4) {
        float4 v = ((const float4*)in)[i];
        __half2 h0 = __floats2half2_rn(v.x, v.y);
        __half2 h1 = __floats2half2_rn(v.z, v.w);
        uint2 st;
        st.x = *(uint32_t*)&h0;
        st.y = *(uint32_t*)&h1;
        ((uint2*)out)[i] = st;
    }
}

// ------------------------------ rmsnorm (fp16 output) -----------------------
__global__ void rmsnorm_kernel(const float* __restrict__ x, const float* __restrict__ w,
                               __half* __restrict__ y) {
    int row = blockIdx.x;
    const float* xr = x + (size_t)row * DMODEL;
    float ss = 0.f;
    for (int c = threadIdx.x; c < DMODEL; c += 256) { float v = xr[c]; ss += v * v; }
    #pragma unroll
    for (int off = 16; off; off >>= 1) ss += __shfl_xor_sync(0xffffffffu, ss, off);
    __shared__ float red[8];
    if ((threadIdx.x & 31) == 0) red[threadIdx.x >> 5] = ss;
    __syncthreads();
    if (threadIdx.x < 8) {
        float v = red[threadIdx.x];
        #pragma unroll
        for (int off = 4; off; off >>= 1) v += __shfl_xor_sync(0xffu, v, off);
        if (threadIdx.x == 0) red[0] = v;
    }
    __syncthreads();
    float inv = rsqrtf(red[0] / (float)DMODEL + 1e-5f);
    __half* yr = y + (size_t)row * DMODEL;
    for (int c = threadIdx.x; c < DMODEL; c += 256)
        yr[c] = __float2half_rn(w[c] * xr[c] * inv);
}

// ------------------------------ FP16 tensor-core GEMM -----------------------
// acc(fp32) = A(fp16) * W(fp16)^T. Epilogue: +res / silu*upg / fp32+fp16 out.
// CTA 128x256, BK=64, 8 warps of 64x64, 3-stage cp.async (proven config).
#define HROW 144
#define ASTGB (128 * HROW)
#define BSTGB (256 * HROW)
#define STGB  (ASTGB + BSTGB)
#define SMEM_HGEMM (3 * STGB)

__global__ __launch_bounds__(256, 1) void hgemm_kernel(
        const __half* __restrict__ A, const __half* __restrict__ W,
        const float* __restrict__ res, const __half* __restrict__ upg,
        float* __restrict__ C, __half* __restrict__ Ch,
        int M, int N, int K) {
    extern __shared__ char smraw[];
    const uint32_t sb = smem_u32(smraw);

    int tid = threadIdx.x;
    int bm = blockIdx.y * 128, bn = blockIdx.x * 256;
    int lane = tid & 31, warp = tid >> 5;
    int wm = (warp >> 2) * 64;
    int wn = (warp & 3) * 64;
    int grp = lane >> 2, tig = lane & 3;

    int mat = lane >> 3, r = lane & 7;
    uint32_t a_off = (uint32_t)(((mat & 1) * 8 + r) * HROW + (mat >> 1) * 16);
    uint32_t b_off = (uint32_t)(((mat >> 1) * 8 + r) * HROW + (mat & 1) * 16);

    float c[4][8][4];
    #pragma unroll
    for (int mt = 0; mt < 4; mt++)
        #pragma unroll
        for (int nt = 0; nt < 8; nt++)
            #pragma unroll
            for (int e = 0; e < 4; e++) c[mt][nt][e] = 0.f;

    const int ldrow = tid >> 3;
    const int c16   = tid & 7;

    auto load_tile = [&](int t, int which) {
        int kb = t * 64;
        uint32_t ab = sb + (uint32_t)which * STGB;
        uint32_t wb = ab + ASTGB;
        #pragma unroll
        for (int i = 0; i < 4; i++) {
            int row = ldrow + i * 32;
            cpa16(ab + row * HROW + c16 * 16,
                  A + (size_t)(bm + row) * K + kb + c16 * 8, 16);
        }
        #pragma unroll
        for (int i = 0; i < 8; i++) {
            int row = ldrow + i * 32;
            int n = bn + row;
            int nn = n < N ? n : (N - 1);
            cpa16(wb + row * HROW + c16 * 16,
                  W + (size_t)nn * K + kb + c16 * 8, n < N ? 16 : 0);
        }
    };

    int ntiles = K / 64;
    load_tile(0, 0); cpa_commit();
    load_tile(1, 1); cpa_commit();

    for (int t = 0; t < ntiles; t++) {
        int buf = t % 3;
        if (t + 1 < ntiles) cpa_wait1(); else cpa_wait0();
        __syncthreads();
        if (t + 2 < ntiles) { load_tile(t + 2, (t + 2) % 3); cpa_commit(); }
        uint32_t ab = sb + (uint32_t)buf * STGB;
        uint32_t wb = ab + ASTGB;
        uint32_t abase = ab + (uint32_t)wm * HROW + a_off;
        uint32_t bbase = wb + (uint32_t)wn * HROW + b_off;
        #pragma unroll
        for (int ks = 0; ks < 4; ks++) {
            uint32_t kbyte = (uint32_t)ks * 32;
            uint32_t af[4][4], bf[8][2];
            #pragma unroll
            for (int mt = 0; mt < 4; mt++)
                LDSM4(af[mt][0], af[mt][1], af[mt][2], af[mt][3],
                      abase + (uint32_t)mt * 16 * HROW + kbyte);
            #pragma unroll
            for (int ntp = 0; ntp < 4; ntp++)
                LDSM4(bf[2*ntp][0], bf[2*ntp][1], bf[2*ntp+1][0], bf[2*ntp+1][1],
                      bbase + (uint32_t)ntp * 16 * HROW + kbyte);
            #pragma unroll
            for (int mt = 0; mt < 4; mt++)
                #pragma unroll
                for (int nt = 0; nt < 8; nt++)
                    HMMA(c[mt][nt][0], c[mt][nt][1], c[mt][nt][2], c[mt][nt][3],
                         af[mt][0], af[mt][1], af[mt][2], af[mt][3],
                         bf[nt][0], bf[nt][1]);
        }
        __syncthreads();
    }

    #pragma unroll
    for (int mt = 0; mt < 4; mt++) {
        int r0 = bm + wm + mt * 16 + grp;
        #pragma unroll
        for (int nt = 0; nt < 8; nt++) {
            int col = bn + wn + nt * 8 + 2 * tig;
            if (col < N) {
                float v0 = c[mt][nt][0], v1 = c[mt][nt][1];
                float v2 = c[mt][nt][2], v3 = c[mt][nt][3];
                size_t o0 = (size_t)r0 * N + col;
                size_t o1 = (size_t)(r0 + 8) * N + col;
                if (res) {
                    v0 += res[o0]; v1 += res[o0 + 1];
                    v2 += res[o1]; v3 += res[o1 + 1];
                }
                if (upg) {
                    __half2 u0 = *(const __half2*)(upg + o0);
                    __half2 u1 = *(const __half2*)(upg + o1);
                    v0 = siluf(v0) * __half2float(u0.x);
                    v1 = siluf(v1) * __half2float(u0.y);
                    v2 = siluf(v2) * __half2float(u1.x);
                    v3 = siluf(v3) * __half2float(u1.y);
                }
                if (C) {
                    *(float2*)(C + o0) = make_float2(v0, v1);
                    *(float2*)(C + o1) = make_float2(v2, v3);
                }
                if (Ch) {
                    *(__half2*)(Ch + o0) = __floats2half2_rn(v0, v1);
                    *(__half2*)(Ch + o1) = __floats2half2_rn(v2, v3);
                }
            }
        }
    }
}

// ------------------------------ causal depthwise conv (fp16 out) ------------
__global__ void conv1d_kernel(const float* __restrict__ zx, const float* __restrict__ cw,
                              const float* __restrict__ cb, __half* __restrict__ xBC) {
    size_t idx = (size_t)blockIdx.x * blockDim.x + threadIdx.x;
    if (idx >= (size_t)MTOK * CONVD) return;
    int c = (int)(idx % CONVD);
    int m = (int)(idx / CONVD);
    int t = m & (LSEQ - 1);
    float acc = cb[c];
    #pragma unroll
    for (int j = 0; j < 4; j++) {
        int tt = t - 3 + j;
        if (tt >= 0)
            acc += cw[c * 4 + j] * zx[(size_t)(m - 3 + j) * DINPROJ + DINNER + c];
    }
    xBC[idx] = __float2half_rn(acc);
}

// ------------------------------ SSD intra-chunk (tensor-core, 512 thr) ------
#define SROW64  144
#define SROW128 272
#define SOFF_CS   0
#define SOFF_BS   18432
#define SOFF_XT   36864
#define SOFF_BD   54272
#define SOFF_SC   71680
#define SOFF_CUM  106496
#define SOFF_DEND 107008
#define SMEM_INTRA 107520

__global__ __launch_bounds__(512) void ssd_intra_kernel(
        const float* __restrict__ zx, const __half* __restrict__ xBC,
        __half* __restrict__ yi, float* __restrict__ Sg,
        float* __restrict__ Ag, float* __restrict__ cumg) {
    extern __shared__ char smraw[];
    const uint32_t sb = smem_u32(smraw);
    __half* Cs = (__half*)(smraw + SOFF_CS);
    __half* Bs = (__half*)(smraw + SOFF_BS);
    __half* xT = (__half*)(smraw + SOFF_XT);
    __half* Bd = (__half*)(smraw + SOFF_BD);
    __half* sc = (__half*)(smraw + SOFF_SC);
    float* cum  = (float*)(smraw + SOFF_CUM);
    float* dend = (float*)(smraw + SOFF_DEND);

    int h = blockIdx.x % NH;
    int c = (blockIdx.x / NH) % NCHUNK;
    int b = blockIdx.x / (NH * NCHUNK);
    int tid = threadIdx.x;
    int lane = tid & 31, warp = tid >> 5;
    int grp = lane >> 2, tig = lane & 3;
    int mat = lane >> 3, r = lane & 7;
    int m0 = b * LSEQ + c * CHUNK;

    for (int idx = tid; idx < CHUNK * 32; idx += 512) {
        int i = idx >> 5, p2 = idx & 31;
        size_t rowb = (size_t)(m0 + i) * CONVD;
        __half2 xv = *(const __half2*)(xBC + rowb + h * HD + 2 * p2);
        __half2 bv = *(const __half2*)(xBC + rowb + DINNER + h * DSTATE + 2 * p2);
        __half2 cv = *(const __half2*)(xBC + rowb + DINNER + NH * DSTATE + h * DSTATE + 2 * p2);
        *(__half2*)(Cs + i * 72 + 2 * p2) = cv;
        *(__half2*)(Bs + i * 72 + 2 * p2) = bv;
        xT[(2 * p2) * 136 + i]     = __low2half(xv);
        xT[(2 * p2 + 1) * 136 + i] = __high2half(xv);
    }
    if (tid < CHUNK) {
        float d = zx[(size_t)(m0 + tid) * DINPROJ + DTOFF + h];
        float sp = (d > 20.f) ? d : log1pf(expf(d));
        cum[tid] = -sp;
    }
    __syncthreads();
    for (int off = 1; off < CHUNK; off <<= 1) {
        float v = 0.f;
        if (tid < CHUNK && tid >= off) v = cum[tid - off];
        __syncthreads();
        if (tid < CHUNK && tid >= off) cum[tid] += v;
        __syncthreads();
    }
    if (tid < CHUNK) dend[tid] = expf(cum[CHUNK - 1] - cum[tid]);
    __syncthreads();

    for (int idx = tid; idx < DSTATE * CHUNK; idx += 512) {
        int n = idx >> 7, j = idx & 127;
        Bd[n * 136 + j] = __float2half_rn(__half2float(Bs[j * 72 + n]) * dend[j]);
    }

    // Phase A: sc = mask(exp) .* (C @ B^T)
    {
        int wr = warp >> 2, wc = warp & 3;
        int i0 = wr * 32, j0 = wc * 32;
        float a[2][4][4];
        #pragma unroll
        for (int mt = 0; mt < 2; mt++)
            #pragma unroll
            for (int nt = 0; nt < 4; nt++)
                #pragma unroll
                for (int e = 0; e < 4; e++) a[mt][nt][e] = 0.f;
        if (wc <= wr) {
            uint32_t abase = sb + SOFF_CS + (uint32_t)(((mat & 1) * 8 + r) * SROW64 + (mat >> 1) * 16)
                           + (uint32_t)i0 * SROW64;
            uint32_t bbase = sb + SOFF_BS + (uint32_t)(((mat >> 1) * 8 + r) * SROW64 + (mat & 1) * 16)
                           + (uint32_t)j0 * SROW64;
            #pragma unroll
            for (int ks = 0; ks < 4; ks++) {
                uint32_t kb = (uint32_t)ks * 32;
                uint32_t af[2][4], bf[4][2];
                LDSM4(af[0][0], af[0][1], af[0][2], af[0][3], abase + kb);
                LDSM4(af[1][0], af[1][1], af[1][2], af[1][3], abase + 16u * SROW64 + kb);
                LDSM4(bf[0][0], bf[0][1], bf[1][0], bf[1][1], bbase + kb);
                LDSM4(bf[2][0], bf[2][1], bf[3][0], bf[3][1], bbase + 16u * SROW64 + kb);
                #pragma unroll
                for (int mt = 0; mt < 2; mt++)
                    #pragma unroll
                    for (int nt = 0; nt < 4; nt++)
                        HMMA(a[mt][nt][0], a[mt][nt][1], a[mt][nt][2], a[mt][nt][3],
                             af[mt][0], af[mt][1], af[mt][2], af[mt][3],
                             bf[nt][0], bf[nt][1]);
            }
        }
        #pragma unroll
        for (int mt = 0; mt < 2; mt++) {
            int i1 = i0 + mt * 16 + grp, i2 = i1 + 8;
            float ci1 = cum[i1], ci2 = cum[i2];
            #pragma unroll
            for (int nt = 0; nt < 4; nt++) {
                int j = j0 + nt * 8 + 2 * tig;
                float cj0 = cum[j], cj1 = cum[j + 1];
                float v0 = (j     <= i1) ? expf(ci1 - cj0) * a[mt][nt][0] : 0.f;
                float v1 = (j + 1 <= i1) ? expf(ci1 - cj1) * a[mt][nt][1] : 0.f;
                float v2 = (j     <= i2) ? expf(ci2 - cj0) * a[mt][nt][2] : 0.f;
                float v3 = (j + 1 <= i2) ? expf(ci2 - cj1) * a[mt][nt][3] : 0.f;
                *(__half2*)(sc + i1 * 136 + j) = __floats2half2_rn(v0, v1);
                *(__half2*)(sc + i2 * 136 + j) = __floats2half2_rn(v2, v3);
            }
        }
    }
    __syncthreads();

    // Phase B: y_intra = sc @ x -> fp16 yi
    {
        int i0 = (warp >> 2) * 32, p0 = (warp & 3) * 16;
        float acc[2][2][4];
        #pragma unroll
        for (int mt = 0; mt < 2; mt++)
            #pragma unroll
            for (int nt = 0; nt < 2; nt++)
                #pragma unroll
                for (int e = 0; e < 4; e++) acc[mt][nt][e] = 0.f;
        uint32_t abase = sb + SOFF_SC + (uint32_t)(((mat & 1) * 8 + r) * SROW128 + (mat >> 1) * 16)
                       + (uint32_t)i0 * SROW128;
        uint32_t bbase = sb + SOFF_XT + (uint32_t)(((mat >> 1) * 8 + r) * SROW128 + (mat & 1) * 16)
                       + (uint32_t)p0 * SROW128;
        #pragma unroll
        for (int ks = 0; ks < 8; ks++) {
            uint32_t kb = (uint32_t)ks * 32;
            uint32_t af[2][4], bf[2][2];
            LDSM4(af[0][0], af[0][1], af[0][2], af[0][3], abase + kb);
            LDSM4(af[1][0], af[1][1], af[1][2], af[1][3], abase + 16u * SROW128 + kb);
            LDSM4(bf[0][0], bf[0][1], bf[1][0], bf[1][1], bbase + kb);
            #pragma unroll
            for (int mt = 0; mt < 2; mt++)
                #pragma unroll
                for (int nt = 0; nt < 2; nt++)
                    HMMA(acc[mt][nt][0], acc[mt][nt][1], acc[mt][nt][2], acc[mt][nt][3],
                         af[mt][0], af[mt][1], af[mt][2], af[mt][3],
                         bf[nt][0], bf[nt][1]);
        }
        #pragma unroll
        for (int mt = 0; mt < 2; mt++) {
            int i1 = i0 + mt * 16 + grp;
            #pragma unroll
            for (int nt = 0; nt < 2; nt++) {
                int p = p0 + nt * 8 + 2 * tig;
                size_t o0 = (size_t)(m0 + i1) * DINNER + h * HD + p;
                size_t o1 = (size_t)(m0 + i1 + 8) * DINNER + h * HD + p;
                *(__half2*)(yi + o0) = __floats2half2_rn(acc[mt][nt][0], acc[mt][nt][1]);
                *(__half2*)(yi + o1) = __floats2half2_rn(acc[mt][nt][2], acc[mt][nt][3]);
            }
        }
    }

    // Phase C: S = Bd @ x
    {
        int n0 = (warp >> 2) * 16, p0 = (warp & 3) * 16;
        float acc[2][4];
        #pragma unroll
        for (int nt = 0; nt < 2; nt++)
            #pragma unroll
            for (int e = 0; e < 4; e++) acc[nt][e] = 0.f;
        uint32_t abase = sb + SOFF_BD + (uint32_t)(((mat & 1) * 8 + r) * SROW128 + (mat >> 1) * 16)
                       + (uint32_t)n0 * SROW128;
        uint32_t bbase = sb + SOFF_XT + (uint32_t)(((mat >> 1) * 8 + r) * SROW128 + (mat & 1) * 16)
                       + (uint32_t)p0 * SROW128;
        #pragma unroll
        for (int ks = 0; ks < 8; ks++) {
            uint32_t kb = (uint32_t)ks * 32;
            uint32_t af[4], bf[2][2];
            LDSM4(af[0], af[1], af[2], af[3], abase + kb);
            LDSM4(bf[0][0], bf[0][1], bf[1][0], bf[1][1], bbase + kb);
            #pragma unroll
            for (int nt = 0; nt < 2; nt++)
                HMMA(acc[nt][0], acc[nt][1], acc[nt][2], acc[nt][3],
                     af[0], af[1], af[2], af[3], bf[nt][0], bf[nt][1]);
        }
        size_t off = ((size_t)((b * NCHUNK + c) * NH + h)) * (DSTATE * HD);
        #pragma unroll
        for (int nt = 0; nt < 2; nt++) {
            int p = p0 + nt * 8 + 2 * tig;
            *(float2*)(Sg + off + (n0 + grp) * HD + p)     = make_float2(acc[nt][0], acc[nt][1]);
            *(float2*)(Sg + off + (n0 + grp + 8) * HD + p) = make_float2(acc[nt][2], acc[nt][3]);
        }
    }

    if (tid == 0) Ag[(b * NCHUNK + c) * NH + h] = expf(cum[CHUNK - 1]);
    if (tid < CHUNK)
        cumg[((size_t)((b * NCHUNK + c) * NH + h)) * CHUNK + tid] = cum[tid];
}

// ------------------------------ inter-chunk state recurrence ----------------
__global__ void state_scan_kernel(const float* __restrict__ Sg, const float* __restrict__ Ag,
                                  float* __restrict__ Hp) {
    int b = blockIdx.x / NH, h = blockIdx.x % NH;
    int tid = threadIdx.x;
    float H[16];
    #pragma unroll
    for (int k = 0; k < 16; k++) H[k] = 0.f;
    for (int c = 0; c < NCHUNK; c++) {
        size_t off = ((size_t)((b * NCHUNK + c) * NH + h)) * (DSTATE * HD);
        float Ac = Ag[(b * NCHUNK + c) * NH + h];
        #pragma unroll
        for (int k = 0; k < 16; k++) {
            int e = tid + k * 256;
            Hp[off + e] = H[k];
            H[k] = Ac * H[k] + Sg[off + e];
        }
    }
}

// ------------------------------ y_inter (tensor-core) + D*x + gating --------
// y_full[i][p] = yi[i][p] + (exp(cum_i)*C[i][:]) @ Hp[:,p] + Dh*x[i][p]
// then yh = y_full * silu(z + zb).  128x64x64 HMMA per (b,c,h) block.
#define YI_CE   0          // 128 rows * 144 B = 18432
#define YI_HT   18432      // 64 rows * 144 B = 9216
#define YI_CUM  27648      // 512 B (holds exp(cum))
#define SMEM_YI 28160

__global__ __launch_bounds__(512) void y_inter_kernel(
        const float* __restrict__ zx, const __half* __restrict__ xBC,
        const float* __restrict__ Hp, const float* __restrict__ cumg,
        const float* __restrict__ Dvec, const float* __restrict__ zb,
        const __half* __restrict__ yi, __half* __restrict__ yh) {
    extern __shared__ char smraw[];
    const uint32_t sb = smem_u32(smraw);
    __half* Ce  = (__half*)(smraw + YI_CE);
    __half* HT  = (__half*)(smraw + YI_HT);
    float*  ecu = (float*)(smraw + YI_CUM);

    int h = blockIdx.x % NH;
    int c = (blockIdx.x / NH) % NCHUNK;
    int b = blockIdx.x / (NH * NCHUNK);
    int tid = threadIdx.x;
    int lane = tid & 31, warp = tid >> 5;
    int grp = lane >> 2, tig = lane & 3;
    int mat = lane >> 3, r = lane & 7;
    int m0 = b * LSEQ + c * CHUNK;
    size_t hoff = (size_t)((b * NCHUNK + c) * NH + h);

    if (tid < CHUNK) ecu[tid] = expf(cumg[hoff * CHUNK + tid]);
    // HT[p][n] = Hp[n][p]  (fp32 -> fp16 transpose)
    for (int idx = tid; idx < DSTATE * HD; idx += 512) {
        int n = idx >> 6, p = idx & 63;
        HT[p * 72 + n] = __float2half_rn(Hp[hoff * (DSTATE * HD) + n * HD + p]);
    }
    __syncthreads();
    // Ce[i][n] = exp(cum_i) * C[i][n]
    for (int idx = tid; idx < CHUNK * 32; idx += 512) {
        int i = idx >> 5, n2 = idx & 31;
        size_t rowb = (size_t)(m0 + i) * CONVD;
        __half2 cv = *(const __half2*)(xBC + rowb + DINNER + NH * DSTATE + h * DSTATE + 2 * n2);
        float e = ecu[i];
        *(__half2*)(Ce + i * 72 + 2 * n2) =
            __floats2half2_rn(e * __half2float(cv.x), e * __half2float(cv.y));
    }
    __syncthreads();

    // GEMM 128x64x64: warp tile 32x16, 4x4 warp grid
    int i0 = (warp >> 2) * 32, p0 = (warp & 3) * 16;
    float acc[2][2][4];
    #pragma unroll
    for (int mt = 0; mt < 2; mt++)
        #pragma unroll
        for (int nt = 0; nt < 2; nt++)
            #pragma unroll
            for (int e = 0; e < 4; e++) acc[mt][nt][e] = 0.f;
    uint32_t abase = sb + YI_CE + (uint32_t)(((mat & 1) * 8 + r) * SROW64 + (mat >> 1) * 16)
                   + (uint32_t)i0 * SROW64;
    uint32_t bbase = sb + YI_HT + (uint32_t)(((mat >> 1) * 8 + r) * SROW64 + (mat & 1) * 16)
                   + (uint32_t)p0 * SROW64;
    #pragma unroll
    for (int ks = 0; ks < 4; ks++) {
        uint32_t kb = (uint32_t)ks * 32;
        uint32_t af[2][4], bf[2][2];
        LDSM4(af[0][0], af[0][1], af[0][2], af[0][3], abase + kb);
        LDSM4(af[1][0], af[1][1], af[1][2], af[1][3], abase + 16u * SROW64 + kb);
        LDSM4(bf[0][0], bf[0][1], bf[1][0], bf[1][1], bbase + kb);
        #pragma unroll
        for (int mt = 0; mt < 2; mt++)
            #pragma unroll
            for (int nt = 0; nt < 2; nt++)
                HMMA(acc[mt][nt][0], acc[mt][nt][1], acc[mt][nt][2], acc[mt][nt][3],
                     af[mt][0], af[mt][1], af[mt][2], af[mt][3],
                     bf[nt][0], bf[nt][1]);
    }

    // epilogue: + yi + Dh*x, gate with silu(z+zb)
    float Dh = Dvec[h];
    #pragma unroll
    for (int mt = 0; mt < 2; mt++) {
        #pragma unroll
        for (int rr = 0; rr < 2; rr++) {
            int i1 = i0 + mt * 16 + grp + rr * 8;
            int m = m0 + i1;
            size_t rowb = (size_t)m * CONVD;
            size_t ybase = (size_t)m * DINNER + h * HD;
            size_t zbase = (size_t)m * DINPROJ + h * HD;
            #pragma unroll
            for (int nt = 0; nt < 2; nt++) {
                int p = p0 + nt * 8 + 2 * tig;
                float a0 = acc[mt][nt][rr * 2 + 0];
                float a1 = acc[mt][nt][rr * 2 + 1];
                __half2 yv = *(const __half2*)(yi + ybase + p);
                __half2 xv = *(const __half2*)(xBC + rowb + h * HD + p);
                float v0 = a0 + __half2float(yv.x) + Dh * __half2float(xv.x);
                float v1 = a1 + __half2float(yv.y) + Dh * __half2float(xv.y);
                float2 zg = *(const float2*)(zx + zbase + p);
                float2 zv = *(const float2*)(zb + h * HD + p);
                float g0 = zg.x + zv.x, g1 = zg.y + zv.y;
                v0 *= siluf(g0);
                v1 *= siluf(g1);
                *(__half2*)(yh + ybase + p) = __floats2half2_rn(v0, v1);
            }
        }
    }
}

// ------------------------------ launch --------------------------------------
extern "C" void kernel_launch(void* const* d_in, const int* in_sizes, int n_in,
                              void* d_out, int out_size) {
    const float* hidden     = (const float*)d_in[0];
    const float* in_proj_w  = (const float*)d_in[1];
    const float* z_bias     = (const float*)d_in[2];
    const float* conv_w     = (const float*)d_in[3];
    const float* conv_b     = (const float*)d_in[4];
    const float* Dvec       = (const float*)d_in[5];
    const float* out_proj_w = (const float*)d_in[6];
    const float* norm1_w    = (const float*)d_in[7];
    const float* norm2_w    = (const float*)d_in[8];
    const float* gate_w     = (const float*)d_in[9];
    const float* up_w       = (const float*)d_in[10];
    const float* down_w     = (const float*)d_in[11];
    float* out = (float*)d_out;

    float *zx, *S, *A, *cumg, *Hp, *h2;
    __half *xbc, *yi, *h1h, *yh, *h3h, *uph, *acth, *wip, *wop, *wg, *wu, *wd;
    cudaGetSymbolAddress((void**)&zx,   g_zx);
    cudaGetSymbolAddress((void**)&xbc,  g_xBC);
    cudaGetSymbolAddress((void**)&yi,   g_yi);
    cudaGetSymbolAddress((void**)&S,    g_S);
    cudaGetSymbolAddress((void**)&A,    g_Ac);
    cudaGetSymbolAddress((void**)&cumg, g_cum);
    cudaGetSymbolAddress((void**)&Hp,   g_Hp);
    cudaGetSymbolAddress((void**)&h2,   g_h2);
    cudaGetSymbolAddress((void**)&h1h,  g_h1h);
    cudaGetSymbolAddress((void**)&yh,   g_yh);
    cudaGetSymbolAddress((void**)&h3h,  g_h3h);
    cudaGetSymbolAddress((void**)&uph,  g_uph);
    cudaGetSymbolAddress((void**)&acth, g_acth);
    cudaGetSymbolAddress((void**)&wip,  g_wip);
    cudaGetSymbolAddress((void**)&wop,  g_wop);
    cudaGetSymbolAddress((void**)&wg,   g_wg);
    cudaGetSymbolAddress((void**)&wu,   g_wu);
    cudaGetSymbolAddress((void**)&wd,   g_wd);

    cudaFuncSetAttribute(ssd_intra_kernel, cudaFuncAttributeMaxDynamicSharedMemorySize, SMEM_INTRA);
    cudaFuncSetAttribute(y_inter_kernel,  cudaFuncAttributeMaxDynamicSharedMemorySize, SMEM_YI);
    cudaFuncSetAttribute(hgemm_kernel,    cudaFuncAttributeMaxDynamicSharedMemorySize, SMEM_HGEMM);

    // 0) convert weights fp32 -> fp16
    {
        auto cc = [&](const float* src, __half* dst, size_t n) {
            int n4 = (int)(n / 4);
            w2h_kernel<<<(n4 + 255) / 256, 256>>>(src, dst, n4);
        };
        cc(in_proj_w,  wip, (size_t)DINPROJ * DMODEL);
        cc(out_proj_w, wop, (size_t)DMODEL * DINNER);
        cc(gate_w,     wg,  (size_t)DFF * DMODEL);
        cc(up_w,       wu,  (size_t)DFF * DMODEL);
        cc(down_w,     wd,  (size_t)DMODEL * DFF);
    }

    // 1) rmsnorm 1 -> fp16
    rmsnorm_kernel<<<MTOK, 256>>>(hidden, norm1_w, h1h);
    // 2) in_proj: zx(fp32) = h1 @ in_proj_w^T
    hgemm_kernel<<<dim3((DINPROJ + 255) / 256, MTOK / 128), 256, SMEM_HGEMM>>>(
        h1h, wip, nullptr, nullptr, zx, nullptr, MTOK, DINPROJ, DMODEL);
    // 3) causal depthwise conv -> fp16 xBC
    conv1d_kernel<<<(int)(((size_t)MTOK * CONVD + 255) / 256), 256>>>(zx, conv_w, conv_b, xbc);
    // 4) SSD intra-chunk (tensor-core)
    ssd_intra_kernel<<<BATCH * NCHUNK * NH, 512, SMEM_INTRA>>>(zx, xbc, yi, S, A, cumg);
    // 5) inter-chunk state recurrence
    state_scan_kernel<<<BATCH * NH, 256>>>(S, A, Hp);
    // 6) y_inter (tensor-core) + D*x + gating -> fp16
    y_inter_kernel<<<BATCH * NCHUNK * NH, 512, SMEM_YI>>>(
        zx, xbc, Hp, cumg, Dvec, z_bias, yi, yh);
    // 7) out_proj + residual: h2(fp32) = y @ out_proj_w^T + hidden
    hgemm_kernel<<<dim3(DMODEL / 256, MTOK / 128), 256, SMEM_HGEMM>>>(
        yh, wop, hidden, nullptr, h2, nullptr, MTOK, DMODEL, DINNER);
    // 8) rmsnorm 2 -> fp16
    rmsnorm_kernel<<<MTOK, 256>>>(h2, norm2_w, h3h);
    // 9) up GEMM -> fp16 uph, then gate GEMM with fused silu*up -> fp16 acth
    hgemm_kernel<<<dim3(DFF / 256, MTOK / 128), 256, SMEM_HGEMM>>>(
        h3h, wu, nullptr, nullptr, nullptr, uph, MTOK, DFF, DMODEL);
    hgemm_kernel<<<dim3(DFF / 256, MTOK / 128), 256, SMEM_HGEMM>>>(
        h3h, wg, nullptr, uph, nullptr, acth, MTOK, DFF, DMODEL);
    // 10) down + residual: out = act @ down_w^T + h2
    hgemm_kernel<<<dim3(DMODEL / 256, MTOK / 128), 256, SMEM_HGEMM>>>(
        acth, wd, h2, nullptr, out, nullptr, MTOK, DMODEL, DFF);
}